// round 1
// baseline (speedup 1.0000x reference)
#include <cuda_runtime.h>
#include <cuda_bf16.h>
#include <math.h>

// ---------------- problem constants ----------------
#define BB    8
#define HH    56
#define WW    56
#define CC    256
#define MM    (BB*HH*WW)       // 25088
#define NHD   8                // heads
#define HD    32               // head dim
#define NWIN  7
#define NREG  49
#define RH    8
#define SS    64               // tokens per region
#define TOPKR 4
#define TS    256              // topk*S
#define K2    32               // TS/8
#define SCALE 0.0625f          // C^-0.5

// ---------------- scratch (static device, no allocs) ----------------
__device__ float g_qkv[MM * 3 * CC];                       // [m][768]
__device__ float g_qseq[BB*NHD*NREG*SS*HD];                // [b][h][r][s][d]
__device__ float g_kseq[BB*NHD*NREG*SS*HD];
__device__ float g_vseq[BB*NHD*NREG*SS*HD];
__device__ float g_qr[BB*NREG*CC];
__device__ float g_kr[BB*NREG*CC];
__device__ int   g_idx[BB*NREG*TOPKR];
__device__ float g_attn_out[MM*CC];                        // [m][c]

// ---------------- SGEMM: C[m][n] = sum_k A[m][k]*W[n][k] + bias[n] ----------------
// BM=BN=64, BK=16, 256 threads, 4x4 per thread. M,N divisible by 64; K by 16.
__global__ void sgemm_nt(const float* __restrict__ A, const float* __restrict__ W,
                         const float* __restrict__ bias, float* __restrict__ Cm,
                         int Md, int Nd, int Kd)
{
    __shared__ float As[16][64];
    __shared__ float Ws[16][64];
    const int tid = threadIdx.x;
    const int tx = tid & 15, ty = tid >> 4;
    const int m0 = blockIdx.y * 64, n0 = blockIdx.x * 64;
    const int lr = tid >> 2;          // 0..63 (row within tile)
    const int lc = (tid & 3) * 4;     // 0,4,8,12 (k offset)

    float acc[4][4];
#pragma unroll
    for (int i = 0; i < 4; i++)
#pragma unroll
        for (int j = 0; j < 4; j++) acc[i][j] = 0.f;

    for (int k0 = 0; k0 < Kd; k0 += 16) {
        float4 av = *(const float4*)&A[(size_t)(m0 + lr) * Kd + k0 + lc];
        float4 wv = *(const float4*)&W[(size_t)(n0 + lr) * Kd + k0 + lc];
        As[lc+0][lr] = av.x; As[lc+1][lr] = av.y; As[lc+2][lr] = av.z; As[lc+3][lr] = av.w;
        Ws[lc+0][lr] = wv.x; Ws[lc+1][lr] = wv.y; Ws[lc+2][lr] = wv.z; Ws[lc+3][lr] = wv.w;
        __syncthreads();
#pragma unroll
        for (int k = 0; k < 16; k++) {
            float4 a = *(const float4*)&As[k][ty * 4];
            float4 b = *(const float4*)&Ws[k][tx * 4];
            float ax[4] = {a.x, a.y, a.z, a.w};
            float bx[4] = {b.x, b.y, b.z, b.w};
#pragma unroll
            for (int i = 0; i < 4; i++)
#pragma unroll
                for (int j = 0; j < 4; j++) acc[i][j] += ax[i] * bx[j];
        }
        __syncthreads();
    }
#pragma unroll
    for (int i = 0; i < 4; i++) {
        int m = m0 + ty * 4 + i;
#pragma unroll
        for (int j = 0; j < 4; j++) {
            int n = n0 + tx * 4 + j;
            Cm[(size_t)m * Nd + n] = acc[i][j] + bias[n];
        }
    }
}

// ---------------- reshape qkv[m][768] -> seq layouts ----------------
__global__ void reshape_kernel()
{
    int li = blockIdx.x * 256 + threadIdx.x;   // total 3*8*8*49*64*32 = 19267584
    int d = li & 31;
    int s = (li >> 5) & 63;
    int r = (li >> 11) % 49;
    int rest = li / (2048 * 49);      // t*64 + b*8 + head
    int head = rest & 7;
    int b = (rest >> 3) & 7;
    int t = rest >> 6;

    int h = (r / 7) * 8 + (s >> 3);
    int w = (r % 7) * 8 + (s & 7);
    int m = b * (HH * WW) + h * WW + w;
    float val = g_qkv[(size_t)m * 768 + t * 256 + head * 32 + d];
    int dst = ((((b * NHD + head) * NREG + r) * SS + s) * HD) + d;
    if (t == 0) g_qseq[dst] = val;
    else if (t == 1) g_kseq[dst] = val;
    else g_vseq[dst] = val;
}

// ---------------- region pooling ----------------
__global__ void pool_kernel()
{
    int i = blockIdx.x * 256 + threadIdx.x;    // B*NREG*C = 100352
    if (i >= BB * NREG * CC) return;
    int c = i & 255;
    int r = (i >> 8) % 49;
    int b = i / (256 * 49);
    int head = c >> 5, d = c & 31;
    int base = (((b * NHD + head) * NREG + r) * SS) * HD + d;
    float sq = 0.f, sk = 0.f;
#pragma unroll 8
    for (int s = 0; s < SS; s++) {
        sq += g_qseq[base + s * HD];
        sk += g_kseq[base + s * HD];
    }
    g_qr[i] = sq * (1.f / 64.f);
    g_kr[i] = sk * (1.f / 64.f);
}

// ---------------- region routing: a_r = q_r @ k_r^T, top-4 ----------------
__global__ void region_topk_kernel()
{
    __shared__ float a[64];
    int bn = blockIdx.x;               // B*NREG blocks
    int b = bn / NREG, nq = bn % NREG;
    int tid = threadIdx.x;
    if (tid < NREG) {
        const float* qv = &g_qr[(b * NREG + nq) * CC];
        const float* kv = &g_kr[(b * NREG + tid) * CC];
        float acc = 0.f;
#pragma unroll 8
        for (int c = 0; c < CC; c++) acc += qv[c] * kv[c];
        a[tid] = acc;
    }
    __syncthreads();
    if (tid == 0) {
        for (int t = 0; t < TOPKR; t++) {
            float bm = -INFINITY; int bi = 0;
            for (int m = 0; m < NREG; m++)
                if (a[m] > bm) { bm = a[m]; bi = m; }   // strict > => lowest index on tie
            g_idx[(b * NREG + nq) * TOPKR + t] = bi;
            a[bi] = -INFINITY;
        }
    }
}

// ---------------- fused attention: scores -> top-32 -> softmax -> a@V ----------------
// one CTA per (b, head, region); 256 threads
__global__ void attn_kernel()
{
    extern __shared__ float sm[];
    float* Qs  = sm;                    // [64][33]
    float* KgS = Qs + 64 * 33;          // [256][33]
    float* VgS = KgS + 256 * 33;        // [256][33]
    float* Sc  = VgS + 256 * 33;        // [64][256]

    int bid = blockIdx.x;
    int n = bid % NREG;
    int head = (bid / NREG) & 7;
    int b = bid / (NREG * NHD);
    int tid = threadIdx.x;

    // load Q
    {
        int qb = (((b * NHD + head) * NREG + n) * SS) * HD;
        for (int i = tid; i < SS * HD; i += 256) {
            Qs[(i >> 5) * 33 + (i & 31)] = g_qseq[qb + i];
        }
    }
    // load gathered K, V (4 regions)
    for (int t = 0; t < TOPKR; t++) {
        int rt = g_idx[(b * NREG + n) * TOPKR + t];
        int kb = (((b * NHD + head) * NREG + rt) * SS) * HD;
        for (int i = tid; i < SS * HD; i += 256) {
            int row = t * SS + (i >> 5);
            int d = i & 31;
            KgS[row * 33 + d] = g_kseq[kb + i];
            VgS[row * 33 + d] = g_vseq[kb + i];
        }
    }
    __syncthreads();

    // scores: thread tid owns key column kk=tid
    {
        float kreg[HD];
#pragma unroll
        for (int d = 0; d < HD; d++) kreg[d] = KgS[tid * 33 + d];
#pragma unroll 4
        for (int s = 0; s < SS; s++) {
            float acc = 0.f;
#pragma unroll
            for (int d = 0; d < HD; d++) acc += Qs[s * 33 + d] * kreg[d];
            Sc[s * 256 + tid] = acc * SCALE;
        }
    }
    __syncthreads();

    // per-warp rows: top-32, softmax, weighted V sum
    int warp = tid >> 5;
    int lane = tid & 31;
    for (int row = warp * 8; row < warp * 8 + 8; row++) {
        float v[8];
#pragma unroll
        for (int i = 0; i < 8; i++) v[i] = Sc[row * 256 + lane + 32 * i];

        float sel_val = 0.f; int sel_idx = 0;
#pragma unroll 1
        for (int k = 0; k < K2; k++) {
            float bm = -INFINITY; int bi = 0x7fffffff;
#pragma unroll
            for (int i = 0; i < 8; i++) {
                int idx = lane + 32 * i;
                if (v[i] > bm) { bm = v[i]; bi = idx; }
            }
#pragma unroll
            for (int off = 16; off; off >>= 1) {
                float ov = __shfl_xor_sync(0xffffffffu, bm, off);
                int oi = __shfl_xor_sync(0xffffffffu, bi, off);
                if (ov > bm || (ov == bm && oi < bi)) { bm = ov; bi = oi; }
            }
            if (lane == k) { sel_val = bm; sel_idx = bi; }
            if ((bi & 31) == lane) v[bi >> 5] = -INFINITY;   // mask winner
        }
        // softmax over the 32 selected (lane k holds k-th largest)
        float mx = __shfl_sync(0xffffffffu, sel_val, 0);
        float e = __expf(sel_val - mx);
        float ssum = e;
#pragma unroll
        for (int off = 16; off; off >>= 1) ssum += __shfl_xor_sync(0xffffffffu, ssum, off);
        float wgt = e / ssum;

        // out[d=lane] = sum_k w_k * V[idx_k][d]
        float outv = 0.f;
#pragma unroll 1
        for (int k = 0; k < K2; k++) {
            float wk = __shfl_sync(0xffffffffu, wgt, k);
            int ik = __shfl_sync(0xffffffffu, sel_idx, k);
            outv += wk * VgS[ik * 33 + lane];
        }
        int h = (n / 7) * 8 + (row >> 3);
        int w = (n % 7) * 8 + (row & 7);
        int m = b * (HH * WW) + h * WW + w;
        g_attn_out[(size_t)m * CC + head * HD + lane] = outv;
    }
}

// ---------------- lepe: 3x3 depthwise conv on v, add into attn_out ----------------
__global__ void lepe_kernel(const float* __restrict__ lepe_w, const float* __restrict__ lepe_b)
{
    int idx = blockIdx.x * 256 + threadIdx.x;   // M*C
    int c = idx & 255;
    int m = idx >> 8;
    int b = m / (HH * WW);
    int hw = m % (HH * WW);
    int h = hw / WW, w = hw % WW;
    int head = c >> 5, d = c & 31;

    float acc = lepe_b[c];
#pragma unroll
    for (int i = 0; i < 3; i++) {
        int hh = h + i - 1;
        if (hh < 0 || hh >= HH) continue;
#pragma unroll
        for (int j = 0; j < 3; j++) {
            int ww = w + j - 1;
            if (ww < 0 || ww >= WW) continue;
            int r = (hh >> 3) * 7 + (ww >> 3);
            int s = ((hh & 7) << 3) + (ww & 7);
            float vv = g_vseq[(((b * NHD + head) * NREG + r) * SS + s) * HD + d];
            acc += vv * lepe_w[c * 9 + i * 3 + j];
        }
    }
    g_attn_out[idx] += acc;
}

// ---------------- launch ----------------
extern "C" void kernel_launch(void* const* d_in, const int* in_sizes, int n_in,
                              void* d_out, int out_size)
{
    const float* x      = (const float*)d_in[0];
    const float* qkv_w  = (const float*)d_in[1];
    const float* qkv_b  = (const float*)d_in[2];
    const float* lepe_w = (const float*)d_in[3];
    const float* lepe_b = (const float*)d_in[4];
    const float* out_w  = (const float*)d_in[5];
    const float* out_b  = (const float*)d_in[6];
    float* out = (float*)d_out;

    float* qkv_buf = nullptr;
    cudaGetSymbolAddress((void**)&qkv_buf, g_qkv);
    float* attn_buf = nullptr;
    cudaGetSymbolAddress((void**)&attn_buf, g_attn_out);

    // 1) QKV GEMM: [25088,256] x [768,256]^T -> [25088,768]
    sgemm_nt<<<dim3(768 / 64, MM / 64), 256>>>(x, qkv_w, qkv_b, qkv_buf, MM, 768, CC);

    // 2) reshape to seq layout
    reshape_kernel<<<(3 * BB * NHD * NREG * SS * HD) / 256, 256>>>();

    // 3) region pooling
    pool_kernel<<<(BB * NREG * CC + 255) / 256, 256>>>();

    // 4) region routing top-4
    region_topk_kernel<<<BB * NREG, 64>>>();

    // 5) fused attention
    {
        int smem = (64 * 33 + 256 * 33 + 256 * 33 + 64 * 256) * (int)sizeof(float);
        cudaFuncSetAttribute(attn_kernel, cudaFuncAttributeMaxDynamicSharedMemorySize, smem);
        attn_kernel<<<BB * NHD * NREG, 256, smem>>>();
    }

    // 6) lepe depthwise conv added into attn_out
    lepe_kernel<<<(MM * CC) / 256, 256>>>(lepe_w, lepe_b);

    // 7) output projection: [25088,256] x [256,256]^T -> d_out
    sgemm_nt<<<dim3(CC / 64, MM / 64), 256>>>(attn_buf, out_w, out_b, out, MM, CC, CC);
}

// round 2
// speedup vs baseline: 1.4197x; 1.4197x over previous
#include <cuda_runtime.h>
#include <cuda_bf16.h>
#include <math.h>

// ---------------- problem constants ----------------
#define BB    8
#define HH    56
#define WW    56
#define CC    256
#define MM    (BB*HH*WW)       // 25088
#define NHD   8
#define HD    32
#define NWIN  7
#define NREG  49
#define SS    64
#define TOPKR 4
#define TS    256
#define K2    32
#define SCALE 0.0625f

// ---------------- scratch ----------------
__device__ float g_qseq[BB*NHD*NREG*SS*HD];
__device__ float g_kseq[BB*NHD*NREG*SS*HD];
__device__ float g_vseq[BB*NHD*NREG*SS*HD];
__device__ float g_qr[BB*NREG*CC];
__device__ float g_kr[BB*NREG*CC];
__device__ int   g_idx[BB*NREG*TOPKR];
__device__ float g_attn_out[MM*CC];

// ============ SGEMM 128x128, BK=8, 256 thr, 8x8/thread, double-buffered ============
// C[m][n] = sum_k A[m][k] * W[n][k] + bias[n]
// EPI=0: store to Cm[m*Nd+n].  EPI=1: scatter into g_{q,k,v}seq (qkv layout).
template<int EPI>
__global__ __launch_bounds__(256, 2)
void sgemm128(const float* __restrict__ A, const float* __restrict__ W,
              const float* __restrict__ bias, float* __restrict__ Cm,
              int Nd, int Kd)
{
    __shared__ float As[2][8][132];
    __shared__ float Bs[2][8][132];

    const int tid = threadIdx.x;
    const int tx = tid & 15, ty = tid >> 4;
    const int m0 = blockIdx.y * 128, n0 = blockIdx.x * 128;
    const int ldr = tid >> 1;            // 0..127
    const int ldc = (tid & 1) * 4;       // 0 or 4

    const float* Ap = A + (size_t)(m0 + ldr) * Kd + ldc;
    const float* Wp = W + (size_t)(n0 + ldr) * Kd + ldc;

    float acc[8][8];
#pragma unroll
    for (int i = 0; i < 8; i++)
#pragma unroll
        for (int j = 0; j < 8; j++) acc[i][j] = 0.f;

    const int nt = Kd >> 3;   // 32

    float4 ra = *(const float4*)Ap;
    float4 rb = *(const float4*)Wp;
    As[0][ldc+0][ldr]=ra.x; As[0][ldc+1][ldr]=ra.y; As[0][ldc+2][ldr]=ra.z; As[0][ldc+3][ldr]=ra.w;
    Bs[0][ldc+0][ldr]=rb.x; Bs[0][ldc+1][ldr]=rb.y; Bs[0][ldc+2][ldr]=rb.z; Bs[0][ldc+3][ldr]=rb.w;
    __syncthreads();

    for (int kt = 0; kt < nt; kt++) {
        const int cur = kt & 1;
        if (kt + 1 < nt) {
            ra = *(const float4*)(Ap + (kt + 1) * 8);
            rb = *(const float4*)(Wp + (kt + 1) * 8);
        }
#pragma unroll
        for (int k = 0; k < 8; k++) {
            float4 a0 = *(const float4*)&As[cur][k][ty * 8];
            float4 a1 = *(const float4*)&As[cur][k][ty * 8 + 4];
            float4 b0 = *(const float4*)&Bs[cur][k][tx * 8];
            float4 b1 = *(const float4*)&Bs[cur][k][tx * 8 + 4];
            float av[8] = {a0.x,a0.y,a0.z,a0.w,a1.x,a1.y,a1.z,a1.w};
            float bv[8] = {b0.x,b0.y,b0.z,b0.w,b1.x,b1.y,b1.z,b1.w};
#pragma unroll
            for (int i = 0; i < 8; i++)
#pragma unroll
                for (int j = 0; j < 8; j++) acc[i][j] += av[i] * bv[j];
        }
        if (kt + 1 < nt) {
            const int nxt = cur ^ 1;
            As[nxt][ldc+0][ldr]=ra.x; As[nxt][ldc+1][ldr]=ra.y; As[nxt][ldc+2][ldr]=ra.z; As[nxt][ldc+3][ldr]=ra.w;
            Bs[nxt][ldc+0][ldr]=rb.x; Bs[nxt][ldc+1][ldr]=rb.y; Bs[nxt][ldc+2][ldr]=rb.z; Bs[nxt][ldc+3][ldr]=rb.w;
        }
        __syncthreads();
    }

    // bias for this thread's 8 columns
    float bn[8];
#pragma unroll
    for (int j = 0; j < 8; j++) bn[j] = bias[n0 + tx * 8 + j];

    if (EPI == 0) {
#pragma unroll
        for (int i = 0; i < 8; i++) {
            int m = m0 + ty * 8 + i;
            float4 o0 = make_float4(acc[i][0]+bn[0], acc[i][1]+bn[1], acc[i][2]+bn[2], acc[i][3]+bn[3]);
            float4 o1 = make_float4(acc[i][4]+bn[4], acc[i][5]+bn[5], acc[i][6]+bn[6], acc[i][7]+bn[7]);
            *(float4*)&Cm[(size_t)m * Nd + n0 + tx * 8]     = o0;
            *(float4*)&Cm[(size_t)m * Nd + n0 + tx * 8 + 4] = o1;
        }
    } else {
        // scatter into q/k/v seq layout: dst = (((b*8+head)*49+r)*64+s)*32+d
#pragma unroll
        for (int i = 0; i < 8; i++) {
            int m = m0 + ty * 8 + i;
            int b = m / 3136;
            int hw = m - b * 3136;
            int h = hw / 56, w = hw - (hw / 56) * 56;
            int r = (h >> 3) * 7 + (w >> 3);
            int s = ((h & 7) << 3) + (w & 7);
#pragma unroll
            for (int j4 = 0; j4 < 2; j4++) {
                int n = n0 + tx * 8 + j4 * 4;
                int t = n >> 8;
                int c = n & 255;
                int head = c >> 5, d = c & 31;
                float* dstb = (t == 0) ? g_qseq : (t == 1) ? g_kseq : g_vseq;
                size_t dst = ((((size_t)(b * 8 + head) * 49 + r) * 64 + s) * 32 + d);
                float4 o = make_float4(acc[i][j4*4+0]+bn[j4*4+0], acc[i][j4*4+1]+bn[j4*4+1],
                                       acc[i][j4*4+2]+bn[j4*4+2], acc[i][j4*4+3]+bn[j4*4+3]);
                *(float4*)&dstb[dst] = o;
            }
        }
    }
}

// ---------------- region pooling ----------------
__global__ void pool_kernel()
{
    int i = blockIdx.x * 256 + threadIdx.x;
    if (i >= BB * NREG * CC) return;
    int c = i & 255;
    int r = (i >> 8) % 49;
    int b = i / (256 * 49);
    int head = c >> 5, d = c & 31;
    int base = (((b * NHD + head) * NREG + r) * SS) * HD + d;
    float sq = 0.f, sk = 0.f;
#pragma unroll 8
    for (int s = 0; s < SS; s++) {
        sq += g_qseq[base + s * HD];
        sk += g_kseq[base + s * HD];
    }
    g_qr[i] = sq * (1.f / 64.f);
    g_kr[i] = sk * (1.f / 64.f);
}

// ---------------- region routing top-4 (smem-staged, coalesced) ----------------
__global__ void region_topk_kernel()
{
    extern __shared__ float rsm[];         // kr[49*257] + qv[256]
    float* kr = rsm;
    float* qv = rsm + 49 * 257;
    __shared__ float a[64];

    int bn = blockIdx.x;
    int b = bn / NREG, nq = bn % NREG;
    int tid = threadIdx.x;

    // coalesced stage of all 49 key-region vectors for this batch
    const float* src = &g_kr[(size_t)b * NREG * CC];
    for (int i = tid; i < NREG * CC; i += 256) {
        int t = i >> 8, c = i & 255;
        kr[t * 257 + c] = src[i];
    }
    // query vector
    const float* qsrc = &g_qr[((size_t)b * NREG + nq) * CC];
    if (tid < CC) qv[tid] = qsrc[tid];
    __syncthreads();

    if (tid < NREG) {
        float accv = 0.f;
        const float* kv = &kr[tid * 257];
#pragma unroll 8
        for (int c = 0; c < CC; c++) accv += qv[c] * kv[c];
        a[tid] = accv;
    }
    __syncthreads();
    if (tid == 0) {
        for (int t = 0; t < TOPKR; t++) {
            float bm = -INFINITY; int bi = 0;
            for (int m = 0; m < NREG; m++)
                if (a[m] > bm) { bm = a[m]; bi = m; }
            g_idx[(b * NREG + nq) * TOPKR + t] = bi;
            a[bi] = -INFINITY;
        }
    }
}

// ---------------- fused attention ----------------
// one CTA per (b, head, region); 256 threads; scores live in registers
#define PAD36 36
__global__ __launch_bounds__(256, 2)
void attn_kernel()
{
    extern __shared__ float sm[];
    float* Qs = sm;                     // [64][36]
    float* Kg = Qs + 64 * PAD36;        // [256][36]
    float* Vg = Kg + 256 * PAD36;       // [256][36]

    int bid = blockIdx.x;
    int n = bid % NREG;
    int head = (bid / NREG) & 7;
    int b = bid / (NREG * NHD);
    int tid = threadIdx.x;
    int warp = tid >> 5, lane = tid & 31;

    // load Q (float4)
    {
        const float4* src = (const float4*)&g_qseq[(((size_t)(b * NHD + head) * NREG + n) * SS) * HD];
        for (int i4 = tid; i4 < 512; i4 += 256) {
            int row = i4 >> 3, dseg = (i4 & 7) * 4;
            *(float4*)&Qs[row * PAD36 + dseg] = src[i4];
        }
    }
    // load gathered K/V
    for (int t = 0; t < TOPKR; t++) {
        int rt = g_idx[(b * NREG + n) * TOPKR + t];
        const float4* ksrc = (const float4*)&g_kseq[(((size_t)(b * NHD + head) * NREG + rt) * SS) * HD];
        const float4* vsrc = (const float4*)&g_vseq[(((size_t)(b * NHD + head) * NREG + rt) * SS) * HD];
        for (int i4 = tid; i4 < 512; i4 += 256) {
            int row = t * SS + (i4 >> 3), dseg = (i4 & 7) * 4;
            *(float4*)&Kg[row * PAD36 + dseg] = ksrc[i4];
            *(float4*)&Vg[row * PAD36 + dseg] = vsrc[i4];
        }
    }
    __syncthreads();

    // scores into registers: acc[r][j] = q[warp*8+r] . k[lane+32*j]
    float acc[8][8];
#pragma unroll
    for (int r = 0; r < 8; r++)
#pragma unroll
        for (int j = 0; j < 8; j++) acc[r][j] = 0.f;

#pragma unroll
    for (int d0 = 0; d0 < 32; d0 += 4) {
        float4 kv[8];
#pragma unroll
        for (int j = 0; j < 8; j++) kv[j] = *(const float4*)&Kg[(lane + 32 * j) * PAD36 + d0];
#pragma unroll
        for (int r = 0; r < 8; r++) {
            float4 qv = *(const float4*)&Qs[(warp * 8 + r) * PAD36 + d0];
#pragma unroll
            for (int j = 0; j < 8; j++) {
                acc[r][j] += qv.x * kv[j].x;
                acc[r][j] += qv.y * kv[j].y;
                acc[r][j] += qv.z * kv[j].z;
                acc[r][j] += qv.w * kv[j].w;
            }
        }
    }
#pragma unroll
    for (int r = 0; r < 8; r++)
#pragma unroll
        for (int j = 0; j < 8; j++) acc[r][j] *= SCALE;

    // per-row: top-32 select, softmax, weighted V sum
#pragma unroll 1
    for (int r = 0; r < 8; r++) {
        float sel_val = 0.f; int sel_idx = 0;
#pragma unroll 1
        for (int k = 0; k < K2; k++) {
            float bm = -INFINITY; int bi = 0x7fffffff;
#pragma unroll
            for (int j = 0; j < 8; j++) {
                int idx = lane + 32 * j;
                if (acc[r][j] > bm) { bm = acc[r][j]; bi = idx; }
            }
#pragma unroll
            for (int off = 16; off; off >>= 1) {
                float ov = __shfl_xor_sync(0xffffffffu, bm, off);
                int oi = __shfl_xor_sync(0xffffffffu, bi, off);
                if (ov > bm || (ov == bm && oi < bi)) { bm = ov; bi = oi; }
            }
            if (lane == k) { sel_val = bm; sel_idx = bi; }
            int slot = bi >> 5;
            if ((bi & 31) == lane) {
#pragma unroll
                for (int j = 0; j < 8; j++)
                    if (j == slot) acc[r][j] = -INFINITY;
            }
        }
        float mx = __shfl_sync(0xffffffffu, sel_val, 0);
        float e = __expf(sel_val - mx);
        float ssum = e;
#pragma unroll
        for (int off = 16; off; off >>= 1) ssum += __shfl_xor_sync(0xffffffffu, ssum, off);
        float wgt = e / ssum;

        float outv = 0.f;
#pragma unroll 1
        for (int k = 0; k < K2; k++) {
            float wk = __shfl_sync(0xffffffffu, wgt, k);
            int ik = __shfl_sync(0xffffffffu, sel_idx, k);
            outv += wk * Vg[ik * PAD36 + lane];
        }
        int row = warp * 8 + r;
        int h = (n / 7) * 8 + (row >> 3);
        int w = (n % 7) * 8 + (row & 7);
        int m = b * (HH * WW) + h * WW + w;
        g_attn_out[(size_t)m * CC + head * HD + lane] = outv;
    }
}

// ---------------- lepe ----------------
__global__ void lepe_kernel(const float* __restrict__ lepe_w, const float* __restrict__ lepe_b)
{
    int idx = blockIdx.x * 256 + threadIdx.x;
    int c = idx & 255;
    int m = idx >> 8;
    int b = m / (HH * WW);
    int hw = m % (HH * WW);
    int h = hw / WW, w = hw % WW;
    int head = c >> 5, d = c & 31;

    float acc = lepe_b[c];
#pragma unroll
    for (int i = 0; i < 3; i++) {
        int hh = h + i - 1;
        if (hh < 0 || hh >= HH) continue;
#pragma unroll
        for (int j = 0; j < 3; j++) {
            int ww = w + j - 1;
            if (ww < 0 || ww >= WW) continue;
            int r = (hh >> 3) * 7 + (ww >> 3);
            int s = ((hh & 7) << 3) + (ww & 7);
            float vv = g_vseq[(((b * NHD + head) * NREG + r) * SS + s) * HD + d];
            acc += vv * lepe_w[c * 9 + i * 3 + j];
        }
    }
    g_attn_out[idx] += acc;
}

// ---------------- launch ----------------
extern "C" void kernel_launch(void* const* d_in, const int* in_sizes, int n_in,
                              void* d_out, int out_size)
{
    const float* x      = (const float*)d_in[0];
    const float* qkv_w  = (const float*)d_in[1];
    const float* qkv_b  = (const float*)d_in[2];
    const float* lepe_w = (const float*)d_in[3];
    const float* lepe_b = (const float*)d_in[4];
    const float* out_w  = (const float*)d_in[5];
    const float* out_b  = (const float*)d_in[6];
    float* out = (float*)d_out;

    float* attn_buf = nullptr;
    cudaGetSymbolAddress((void**)&attn_buf, g_attn_out);

    // 1) QKV GEMM fused with reshape scatter
    sgemm128<1><<<dim3(768 / 128, MM / 128), 256>>>(x, qkv_w, qkv_b, nullptr, 768, CC);

    // 2) region pooling
    pool_kernel<<<(BB * NREG * CC + 255) / 256, 256>>>();

    // 3) region routing top-4
    {
        int smem = (49 * 257 + 256) * (int)sizeof(float);
        cudaFuncSetAttribute(region_topk_kernel, cudaFuncAttributeMaxDynamicSharedMemorySize, smem);
        region_topk_kernel<<<BB * NREG, 256, smem>>>();
    }

    // 4) fused attention
    {
        int smem = (64 * PAD36 + 2 * 256 * PAD36) * (int)sizeof(float);
        cudaFuncSetAttribute(attn_kernel, cudaFuncAttributeMaxDynamicSharedMemorySize, smem);
        attn_kernel<<<BB * NHD * NREG, 256, smem>>>();
    }

    // 5) lepe
    lepe_kernel<<<(MM * CC) / 256, 256>>>(lepe_w, lepe_b);

    // 6) output projection
    sgemm128<0><<<dim3(CC / 128, MM / 128), 256>>>(attn_buf, out_w, out_b, out, CC, CC);
}

// round 4
// speedup vs baseline: 2.5856x; 1.8212x over previous
#include <cuda_runtime.h>
#include <cuda_bf16.h>
#include <math.h>

// ---------------- problem constants ----------------
#define BB    8
#define HH    56
#define WW    56
#define CC    256
#define MM    (BB*HH*WW)       // 25088
#define NHD   8
#define HD    32
#define NWIN  7
#define NREG  49
#define SS    64
#define TOPKR 4
#define TS    256
#define K2    32
#define SCALE 0.0625f

// ---------------- scratch ----------------
__device__ float g_qseq[BB*NHD*NREG*SS*HD];
__device__ float g_kseq[BB*NHD*NREG*SS*HD];
__device__ float g_vseq[BB*NHD*NREG*SS*HD];
__device__ float g_vhwc[MM*CC];
__device__ float g_qr[BB*NREG*CC];
__device__ float g_kr[BB*NREG*CC];
__device__ int   g_idx[BB*NREG*TOPKR];
__device__ float g_attn_out[MM*CC];

// ============================================================
// 3xTF32 tensor-core GEMM (near-fp32): C = A @ W^T + bias
// 128x128 tile, BK=16, 256 threads, 8 warps (2M x 4N), warp tile 64x32.
// smem layout [k][136] (136 % 32 == 8 -> conflict-free frags).
// EPI=1: scatter into q/k/v seq layout (+ NHWC V copy).
// ============================================================
#define TLD 136

__device__ __forceinline__ unsigned f2tf32(float x)
{
    unsigned r;
    asm("cvt.rna.tf32.f32 %0, %1;" : "=r"(r) : "f"(x));
    return r;
}

#define MMA_TF32(c, a, b) asm volatile( \
    "mma.sync.aligned.m16n8k8.row.col.f32.tf32.tf32.f32 " \
    "{%0,%1,%2,%3},{%4,%5,%6,%7},{%8,%9},{%0,%1,%2,%3};" \
    : "+f"(c[0]), "+f"(c[1]), "+f"(c[2]), "+f"(c[3]) \
    : "r"(a[0]), "r"(a[1]), "r"(a[2]), "r"(a[3]), "r"(b[0]), "r"(b[1]))

template<int EPI>
__global__ __launch_bounds__(256)
void tf32_gemm(const float* __restrict__ A, const float* __restrict__ W,
               const float* __restrict__ bias, float* __restrict__ Cm, int Nd)
{
    extern __shared__ __align__(16) char smem_raw[];
    unsigned* Ah = (unsigned*)smem_raw;            // [2][16][TLD]
    unsigned* Al = Ah + 2 * 16 * TLD;
    unsigned* Wh = Al + 2 * 16 * TLD;
    unsigned* Wl = Wh + 2 * 16 * TLD;
    float* Cs = (float*)smem_raw;                  // reuse: [128][132]

    const int tid = threadIdx.x;
    const int warp = tid >> 5, lane = tid & 31;
    const int wm = (warp >> 2) * 64, wn = (warp & 3) * 32;
    const int m0 = blockIdx.y * 128, n0 = blockIdx.x * 128;
    const int qrow = lane >> 2, qk = lane & 3;

    float c[4][4][4];
#pragma unroll
    for (int mt = 0; mt < 4; mt++)
#pragma unroll
        for (int nt = 0; nt < 4; nt++)
#pragma unroll
            for (int i = 0; i < 4; i++) c[mt][nt][i] = 0.f;

    auto stage = [&](int kt, int buf) {
        unsigned* ah = Ah + buf * 16 * TLD;
        unsigned* al = Al + buf * 16 * TLD;
        unsigned* wh = Wh + buf * 16 * TLD;
        unsigned* wl = Wl + buf * 16 * TLD;
#pragma unroll
        for (int i = 0; i < 2; i++) {
            int idx = tid + i * 256;               // 0..511
            int row = idx >> 2, kseg = (idx & 3) * 4;
            float4 a = *(const float4*)&A[(size_t)(m0 + row) * 256 + kt * 16 + kseg];
            float4 w = *(const float4*)&W[(size_t)(n0 + row) * 256 + kt * 16 + kseg];
            float av[4] = {a.x, a.y, a.z, a.w};
            float wv[4] = {w.x, w.y, w.z, w.w};
#pragma unroll
            for (int q = 0; q < 4; q++) {
                unsigned hb = f2tf32(av[q]);
                ah[(kseg + q) * TLD + row] = hb;
                al[(kseg + q) * TLD + row] = f2tf32(av[q] - __uint_as_float(hb));
                unsigned whb = f2tf32(wv[q]);
                wh[(kseg + q) * TLD + row] = whb;
                wl[(kseg + q) * TLD + row] = f2tf32(wv[q] - __uint_as_float(whb));
            }
        }
    };

    auto compute = [&](int buf) {
        const unsigned* ah_ = Ah + buf * 16 * TLD;
        const unsigned* al_ = Al + buf * 16 * TLD;
        const unsigned* wh_ = Wh + buf * 16 * TLD;
        const unsigned* wl_ = Wl + buf * 16 * TLD;
#pragma unroll
        for (int ch = 0; ch < 2; ch++) {
            const int kc = ch * 8 + qk;
            unsigned ah[4][4], al[4][4], bh[4][2], bl[4][2];
#pragma unroll
            for (int mt = 0; mt < 4; mt++) {
                int r0 = wm + mt * 16 + qrow;
                ah[mt][0] = ah_[kc * TLD + r0];
                ah[mt][1] = ah_[kc * TLD + r0 + 8];
                ah[mt][2] = ah_[(kc + 4) * TLD + r0];
                ah[mt][3] = ah_[(kc + 4) * TLD + r0 + 8];
                al[mt][0] = al_[kc * TLD + r0];
                al[mt][1] = al_[kc * TLD + r0 + 8];
                al[mt][2] = al_[(kc + 4) * TLD + r0];
                al[mt][3] = al_[(kc + 4) * TLD + r0 + 8];
            }
#pragma unroll
            for (int nt = 0; nt < 4; nt++) {
                int r0 = wn + nt * 8 + qrow;
                bh[nt][0] = wh_[kc * TLD + r0];
                bh[nt][1] = wh_[(kc + 4) * TLD + r0];
                bl[nt][0] = wl_[kc * TLD + r0];
                bl[nt][1] = wl_[(kc + 4) * TLD + r0];
            }
#pragma unroll
            for (int mt = 0; mt < 4; mt++)
#pragma unroll
                for (int nt = 0; nt < 4; nt++) {
                    MMA_TF32(c[mt][nt], ah[mt], bh[nt]);
                    MMA_TF32(c[mt][nt], ah[mt], bl[nt]);
                    MMA_TF32(c[mt][nt], al[mt], bh[nt]);
                }
        }
    };

    stage(0, 0);
    __syncthreads();
#pragma unroll 1
    for (int kt = 0; kt < 16; kt++) {
        const int cur = kt & 1;
        compute(cur);
        if (kt + 1 < 16) stage(kt + 1, cur ^ 1);
        __syncthreads();
    }

    // frags -> smem (fp32) -> coalesced epilogue
#pragma unroll
    for (int mt = 0; mt < 4; mt++)
#pragma unroll
        for (int nt = 0; nt < 4; nt++) {
            int row = wm + mt * 16 + qrow;
            int col = wn + nt * 8 + 2 * qk;
            Cs[row * 132 + col]           = c[mt][nt][0];
            Cs[row * 132 + col + 1]       = c[mt][nt][1];
            Cs[(row + 8) * 132 + col]     = c[mt][nt][2];
            Cs[(row + 8) * 132 + col + 1] = c[mt][nt][3];
        }
    __syncthreads();

#pragma unroll 1
    for (int j = 0; j < 16; j++) {
        int f4 = tid + j * 256;
        int row = f4 >> 5, c4 = (f4 & 31) * 4;
        float4 v = *(float4*)&Cs[row * 132 + c4];
        int n = n0 + c4;
        float4 bn = *(const float4*)&bias[n];
        v.x += bn.x; v.y += bn.y; v.z += bn.z; v.w += bn.w;
        int m = m0 + row;
        if (EPI == 0) {
            *(float4*)&Cm[(size_t)m * Nd + n] = v;
        } else {
            int b = m / 3136;
            int hw = m - b * 3136;
            int h = hw / 56, w = hw - (hw / 56) * 56;
            int r = (h >> 3) * 7 + (w >> 3);
            int s = ((h & 7) << 3) + (w & 7);
            int t = n >> 8;
            int cch = n & 255;
            int head = cch >> 5, d = cch & 31;
            float* dstb = (t == 0) ? g_qseq : (t == 1) ? g_kseq : g_vseq;
            size_t dst = ((((size_t)(b * 8 + head) * 49 + r) * 64 + s) * 32 + d);
            *(float4*)&dstb[dst] = v;
            if (t == 2) *(float4*)&g_vhwc[(size_t)m * 256 + cch] = v;
        }
    }
}

// ============================================================
// bf16x3 tensor-core GEMM (output projection only — no top-k downstream)
// ============================================================
#define LDK 40

#define MMA_BF16(c, a, b) asm volatile( \
    "mma.sync.aligned.m16n8k16.row.col.f32.bf16.bf16.f32 " \
    "{%0,%1,%2,%3},{%4,%5,%6,%7},{%8,%9},{%0,%1,%2,%3};" \
    : "+f"(c[0]), "+f"(c[1]), "+f"(c[2]), "+f"(c[3]) \
    : "r"(a[0]), "r"(a[1]), "r"(a[2]), "r"(a[3]), "r"(b[0]), "r"(b[1]))

__device__ __forceinline__ void split_store(__nv_bfloat16* dh, __nv_bfloat16* dl, float4 a)
{
    __nv_bfloat16 h0 = __float2bfloat16(a.x);
    __nv_bfloat16 h1 = __float2bfloat16(a.y);
    __nv_bfloat16 h2 = __float2bfloat16(a.z);
    __nv_bfloat16 h3 = __float2bfloat16(a.w);
    float l0 = a.x - __bfloat162float(h0);
    float l1 = a.y - __bfloat162float(h1);
    float l2 = a.z - __bfloat162float(h2);
    float l3 = a.w - __bfloat162float(h3);
    ((__nv_bfloat162*)dh)[0] = __halves2bfloat162(h0, h1);
    ((__nv_bfloat162*)dh)[1] = __halves2bfloat162(h2, h3);
    ((__nv_bfloat162*)dl)[0] = __floats2bfloat162_rn(l0, l1);
    ((__nv_bfloat162*)dl)[1] = __floats2bfloat162_rn(l2, l3);
}

__global__ __launch_bounds__(256)
void bf16_gemm(const float* __restrict__ A, const float* __restrict__ W,
               const float* __restrict__ bias, float* __restrict__ Cm, int Nd)
{
    extern __shared__ __align__(16) char smem_raw[];
    __nv_bfloat16* Ah = (__nv_bfloat16*)smem_raw;
    __nv_bfloat16* Al = Ah + 2 * 128 * LDK;
    __nv_bfloat16* Wh = Al + 2 * 128 * LDK;
    __nv_bfloat16* Wl = Wh + 2 * 128 * LDK;
    float* Cs = (float*)smem_raw;

    const int tid = threadIdx.x;
    const int warp = tid >> 5, lane = tid & 31;
    const int wm = (warp >> 2) * 64, wn = (warp & 3) * 32;
    const int m0 = blockIdx.y * 128, n0 = blockIdx.x * 128;

    float c[4][4][4];
#pragma unroll
    for (int mt = 0; mt < 4; mt++)
#pragma unroll
        for (int nt = 0; nt < 4; nt++)
#pragma unroll
            for (int i = 0; i < 4; i++) c[mt][nt][i] = 0.f;

    auto stage = [&](int kt, int buf) {
#pragma unroll
        for (int i = 0; i < 4; i++) {
            int idx = tid + i * 256;
            int row = idx >> 3, seg = (idx & 7) * 4;
            float4 a = *(const float4*)&A[(size_t)(m0 + row) * 256 + kt * 32 + seg];
            float4 w = *(const float4*)&W[(size_t)(n0 + row) * 256 + kt * 32 + seg];
            split_store(Ah + buf * 128 * LDK + row * LDK + seg,
                        Al + buf * 128 * LDK + row * LDK + seg, a);
            split_store(Wh + buf * 128 * LDK + row * LDK + seg,
                        Wl + buf * 128 * LDK + row * LDK + seg, w);
        }
    };

    auto compute = [&](int buf) {
        const __nv_bfloat16* Abh = Ah + buf * 128 * LDK;
        const __nv_bfloat16* Abl = Al + buf * 128 * LDK;
        const __nv_bfloat16* Wbh = Wh + buf * 128 * LDK;
        const __nv_bfloat16* Wbl = Wl + buf * 128 * LDK;
#pragma unroll
        for (int ks = 0; ks < 2; ks++) {
            const int kc = ks * 16 + 2 * (lane & 3);
            unsigned ah[4][4], al[4][4], bh[4][2], bl[4][2];
#pragma unroll
            for (int mt = 0; mt < 4; mt++) {
                int r0 = wm + mt * 16 + (lane >> 2);
                ah[mt][0] = *(const unsigned*)&Abh[r0 * LDK + kc];
                ah[mt][1] = *(const unsigned*)&Abh[(r0 + 8) * LDK + kc];
                ah[mt][2] = *(const unsigned*)&Abh[r0 * LDK + kc + 8];
                ah[mt][3] = *(const unsigned*)&Abh[(r0 + 8) * LDK + kc + 8];
                al[mt][0] = *(const unsigned*)&Abl[r0 * LDK + kc];
                al[mt][1] = *(const unsigned*)&Abl[(r0 + 8) * LDK + kc];
                al[mt][2] = *(const unsigned*)&Abl[r0 * LDK + kc + 8];
                al[mt][3] = *(const unsigned*)&Abl[(r0 + 8) * LDK + kc + 8];
            }
#pragma unroll
            for (int nt = 0; nt < 4; nt++) {
                int r0 = wn + nt * 8 + (lane >> 2);
                bh[nt][0] = *(const unsigned*)&Wbh[r0 * LDK + kc];
                bh[nt][1] = *(const unsigned*)&Wbh[r0 * LDK + kc + 8];
                bl[nt][0] = *(const unsigned*)&Wbl[r0 * LDK + kc];
                bl[nt][1] = *(const unsigned*)&Wbl[r0 * LDK + kc + 8];
            }
#pragma unroll
            for (int mt = 0; mt < 4; mt++)
#pragma unroll
                for (int nt = 0; nt < 4; nt++) {
                    MMA_BF16(c[mt][nt], ah[mt], bh[nt]);
                    MMA_BF16(c[mt][nt], ah[mt], bl[nt]);
                    MMA_BF16(c[mt][nt], al[mt], bh[nt]);
                }
        }
    };

    stage(0, 0);
    __syncthreads();
#pragma unroll 1
    for (int kt = 0; kt < 8; kt++) {
        const int cur = kt & 1;
        compute(cur);
        if (kt + 1 < 8) stage(kt + 1, cur ^ 1);
        __syncthreads();
    }

#pragma unroll
    for (int mt = 0; mt < 4; mt++)
#pragma unroll
        for (int nt = 0; nt < 4; nt++) {
            int row = wm + mt * 16 + (lane >> 2);
            int col = wn + nt * 8 + 2 * (lane & 3);
            Cs[row * 132 + col]           = c[mt][nt][0];
            Cs[row * 132 + col + 1]       = c[mt][nt][1];
            Cs[(row + 8) * 132 + col]     = c[mt][nt][2];
            Cs[(row + 8) * 132 + col + 1] = c[mt][nt][3];
        }
    __syncthreads();

#pragma unroll 1
    for (int j = 0; j < 16; j++) {
        int f4 = tid + j * 256;
        int row = f4 >> 5, c4 = (f4 & 31) * 4;
        float4 v = *(float4*)&Cs[row * 132 + c4];
        int n = n0 + c4;
        float4 bn = *(const float4*)&bias[n];
        v.x += bn.x; v.y += bn.y; v.z += bn.z; v.w += bn.w;
        int m = m0 + row;
        *(float4*)&Cm[(size_t)m * Nd + n] = v;
    }
}

// ---------------- region pooling ----------------
__global__ void pool_kernel()
{
    int i = blockIdx.x * 256 + threadIdx.x;
    if (i >= BB * NREG * CC) return;
    int c = i & 255;
    int r = (i >> 8) % 49;
    int b = i / (256 * 49);
    int head = c >> 5, d = c & 31;
    int base = (((b * NHD + head) * NREG + r) * SS) * HD + d;
    float sq = 0.f, sk = 0.f;
#pragma unroll 8
    for (int s = 0; s < SS; s++) {
        sq += g_qseq[base + s * HD];
        sk += g_kseq[base + s * HD];
    }
    g_qr[i] = sq * (1.f / 64.f);
    g_kr[i] = sk * (1.f / 64.f);
}

// ---------------- region routing top-4 ----------------
__global__ void region_topk_kernel()
{
    extern __shared__ float rsm[];
    float* kr = rsm;
    float* qv = rsm + 49 * 257;
    __shared__ float a[64];

    int bn = blockIdx.x;
    int b = bn / NREG, nq = bn % NREG;
    int tid = threadIdx.x;

    const float* src = &g_kr[(size_t)b * NREG * CC];
    for (int i = tid; i < NREG * CC; i += 256) {
        int t = i >> 8, c = i & 255;
        kr[t * 257 + c] = src[i];
    }
    const float* qsrc = &g_qr[((size_t)b * NREG + nq) * CC];
    if (tid < CC) qv[tid] = qsrc[tid];
    __syncthreads();

    if (tid < NREG) {
        float accv = 0.f;
        const float* kv = &kr[tid * 257];
#pragma unroll 8
        for (int c = 0; c < CC; c++) accv += qv[c] * kv[c];
        a[tid] = accv;
    }
    __syncthreads();
    if (tid == 0) {
        for (int t = 0; t < TOPKR; t++) {
            float bm = -INFINITY; int bi = 0;
            for (int m = 0; m < NREG; m++)
                if (a[m] > bm) { bm = a[m]; bi = m; }
            g_idx[(b * NREG + nq) * TOPKR + t] = bi;
            a[bi] = -INFINITY;
        }
    }
}

// ---------------- fused attention ----------------
#define PAD36 36
#define CE(x, y) { if (u[x] < u[y]) { unsigned tu = u[x]; u[x] = u[y]; u[y] = tu; \
                                      unsigned ti = id[x]; id[x] = id[y]; id[y] = ti; } }

__global__ __launch_bounds__(256, 2)
void attn_kernel()
{
    extern __shared__ float sm[];
    float* Qs = sm;
    float* Kg = Qs + 64 * PAD36;
    float* Vg = Kg + 256 * PAD36;

    int bid = blockIdx.x;
    int n = bid % NREG;
    int head = (bid / NREG) & 7;
    int b = bid / (NREG * NHD);
    int tid = threadIdx.x;
    int warp = tid >> 5, lane = tid & 31;

    {
        const float4* src = (const float4*)&g_qseq[(((size_t)(b * NHD + head) * NREG + n) * SS) * HD];
        for (int i4 = tid; i4 < 512; i4 += 256) {
            int row = i4 >> 3, dseg = (i4 & 7) * 4;
            *(float4*)&Qs[row * PAD36 + dseg] = src[i4];
        }
    }
    for (int t = 0; t < TOPKR; t++) {
        int rt = g_idx[(b * NREG + n) * TOPKR + t];
        const float4* ksrc = (const float4*)&g_kseq[(((size_t)(b * NHD + head) * NREG + rt) * SS) * HD];
        const float4* vsrc = (const float4*)&g_vseq[(((size_t)(b * NHD + head) * NREG + rt) * SS) * HD];
        for (int i4 = tid; i4 < 512; i4 += 256) {
            int row = t * SS + (i4 >> 3), dseg = (i4 & 7) * 4;
            *(float4*)&Kg[row * PAD36 + dseg] = ksrc[i4];
            *(float4*)&Vg[row * PAD36 + dseg] = vsrc[i4];
        }
    }
    __syncthreads();

    float acc[8][8];
#pragma unroll
    for (int r = 0; r < 8; r++)
#pragma unroll
        for (int j = 0; j < 8; j++) acc[r][j] = 0.f;

#pragma unroll
    for (int d0 = 0; d0 < 32; d0 += 4) {
        float4 kv[8];
#pragma unroll
        for (int j = 0; j < 8; j++) kv[j] = *(const float4*)&Kg[(lane + 32 * j) * PAD36 + d0];
#pragma unroll
        for (int r = 0; r < 8; r++) {
            float4 qv = *(const float4*)&Qs[(warp * 8 + r) * PAD36 + d0];
#pragma unroll
            for (int j = 0; j < 8; j++) {
                acc[r][j] += qv.x * kv[j].x;
                acc[r][j] += qv.y * kv[j].y;
                acc[r][j] += qv.z * kv[j].z;
                acc[r][j] += qv.w * kv[j].w;
            }
        }
    }

#pragma unroll 1
    for (int r = 0; r < 8; r++) {
        unsigned u[8], id[8];
#pragma unroll
        for (int j = 0; j < 8; j++) {
            unsigned bts = __float_as_uint(acc[r][j]);
            u[j] = (bts & 0x80000000u) ? ~bts : (bts | 0x80000000u);
            id[j] = lane + 32 * j;
        }
        CE(0,1) CE(2,3) CE(4,5) CE(6,7)
        CE(0,2) CE(1,3) CE(4,6) CE(5,7)
        CE(1,2) CE(5,6)
        CE(0,4) CE(1,5) CE(2,6) CE(3,7)
        CE(2,4) CE(3,5)
        CE(1,2) CE(3,4) CE(5,6)

        unsigned selu = 0, selidx = 0;
#pragma unroll 1
        for (int k = 0; k < K2; k++) {
            unsigned g = __reduce_max_sync(0xffffffffu, u[0]);
            unsigned cand = (u[0] == g) ? id[0] : 0xffffffffu;
            unsigned widx = __reduce_min_sync(0xffffffffu, cand);
            if (lane == k) { selu = g; selidx = widx; }
            if (cand == widx) {
                u[0]=u[1]; id[0]=id[1]; u[1]=u[2]; id[1]=id[2];
                u[2]=u[3]; id[2]=id[3]; u[3]=u[4]; id[3]=id[4];
                u[4]=u[5]; id[4]=id[5]; u[5]=u[6]; id[5]=id[6];
                u[6]=u[7]; id[6]=id[7]; u[7]=0;    id[7]=0xffffffffu;
            }
        }
        float selfv = (selu & 0x80000000u) ? __uint_as_float(selu ^ 0x80000000u)
                                           : __uint_as_float(~selu);
        float mx = __shfl_sync(0xffffffffu, selfv, 0);
        float e = __expf((selfv - mx) * SCALE);
        float ssum = e;
#pragma unroll
        for (int off = 16; off; off >>= 1) ssum += __shfl_xor_sync(0xffffffffu, ssum, off);
        float wgt = e / ssum;

        float outv = 0.f;
#pragma unroll 1
        for (int k = 0; k < K2; k++) {
            float wk = __shfl_sync(0xffffffffu, wgt, k);
            int ik = __shfl_sync(0xffffffffu, (int)selidx, k);
            outv += wk * Vg[ik * PAD36 + lane];
        }
        int row = warp * 8 + r;
        int h = (n / 7) * 8 + (row >> 3);
        int w = (n % 7) * 8 + (row & 7);
        int m = b * (HH * WW) + h * WW + w;
        g_attn_out[(size_t)m * CC + head * HD + lane] = outv;
    }
}

// ---------------- lepe (reads NHWC V copy, coalesced) ----------------
__global__ void lepe_kernel(const float* __restrict__ lepe_w, const float* __restrict__ lepe_b)
{
    int idx = blockIdx.x * 256 + threadIdx.x;
    int c = idx & 255;
    int m = idx >> 8;
    int b = m / (HH * WW);
    int hw = m % (HH * WW);
    int h = hw / WW, w = hw % WW;

    float acc = lepe_b[c];
#pragma unroll
    for (int i = 0; i < 3; i++) {
        int hh = h + i - 1;
        if (hh < 0 || hh >= HH) continue;
#pragma unroll
        for (int j = 0; j < 3; j++) {
            int ww = w + j - 1;
            if (ww < 0 || ww >= WW) continue;
            float vv = g_vhwc[((size_t)(b * 3136) + hh * 56 + ww) * 256 + c];
            acc += vv * lepe_w[c * 9 + i * 3 + j];
        }
    }
    g_attn_out[idx] += acc;
}

// ---------------- launch ----------------
extern "C" void kernel_launch(void* const* d_in, const int* in_sizes, int n_in,
                              void* d_out, int out_size)
{
    const float* x      = (const float*)d_in[0];
    const float* qkv_w  = (const float*)d_in[1];
    const float* qkv_b  = (const float*)d_in[2];
    const float* lepe_w = (const float*)d_in[3];
    const float* lepe_b = (const float*)d_in[4];
    const float* out_w  = (const float*)d_in[5];
    const float* out_b  = (const float*)d_in[6];
    float* out = (float*)d_out;

    float* attn_buf = nullptr;
    cudaGetSymbolAddress((void**)&attn_buf, g_attn_out);

    const int tf32_smem = 4 * 2 * 16 * TLD * 4;                 // 69632
    const int bf16_smem = 2 * 128 * LDK * 4 * (int)sizeof(__nv_bfloat16);  // 81920
    cudaFuncSetAttribute(tf32_gemm<1>, cudaFuncAttributeMaxDynamicSharedMemorySize, tf32_smem);
    cudaFuncSetAttribute(bf16_gemm, cudaFuncAttributeMaxDynamicSharedMemorySize, bf16_smem);

    // 1) QKV GEMM (3xTF32, near-fp32) fused with reshape scatter
    tf32_gemm<1><<<dim3(768 / 128, MM / 128), 256, tf32_smem>>>(x, qkv_w, qkv_b, nullptr, 768);

    // 2) region pooling
    pool_kernel<<<(BB * NREG * CC + 255) / 256, 256>>>();

    // 3) region routing top-4
    {
        int smem = (49 * 257 + 256) * (int)sizeof(float);
        cudaFuncSetAttribute(region_topk_kernel, cudaFuncAttributeMaxDynamicSharedMemorySize, smem);
        region_topk_kernel<<<BB * NREG, 256, smem>>>();
    }

    // 4) fused attention
    {
        int smem = (64 * PAD36 + 2 * 256 * PAD36) * (int)sizeof(float);
        cudaFuncSetAttribute(attn_kernel, cudaFuncAttributeMaxDynamicSharedMemorySize, smem);
        attn_kernel<<<BB * NHD * NREG, 256, smem>>>();
    }

    // 5) lepe
    lepe_kernel<<<(MM * CC) / 256, 256>>>(lepe_w, lepe_b);

    // 6) output projection (bf16x3 — no selection downstream, error ~1e-5)
    bf16_gemm<<<dim3(CC / 128, MM / 128), 256, bf16_smem>>>(attn_buf, out_w, out_b, out, 256);
}

// round 5
// speedup vs baseline: 2.9629x; 1.1459x over previous
#include <cuda_runtime.h>
#include <cuda_bf16.h>
#include <math.h>

// ---------------- problem constants ----------------
#define BB    8
#define HH    56
#define WW    56
#define CC    256
#define MM    (BB*HH*WW)       // 25088
#define NHD   8
#define HD    32
#define NWIN  7
#define NREG  49
#define SS    64
#define TOPKR 4
#define TS    256
#define K2    32
#define SCALE 0.0625f

// ---------------- scratch ----------------
__device__ float g_qseq[BB*NHD*NREG*SS*HD];
__device__ float g_kseq[BB*NHD*NREG*SS*HD];
__device__ float g_vseq[BB*NHD*NREG*SS*HD];
__device__ float g_vhwc[MM*CC];
__device__ float g_qr[BB*NREG*CC];
__device__ float g_kr[BB*NREG*CC];
__device__ int   g_idx[BB*NREG*TOPKR];
__device__ float g_attn_out[MM*CC];

// ============================================================
// TF32 split tensor-core GEMM: C = A @ W^T + bias
// TERMS=6: 3-split (h,m,l) per operand, pairs with pa+pb<3 -> fp32-faithful.
// TERMS=3: 2-split (h,l), pairs hh,hl,lh -> ~2^-21 relative (linear paths).
// 128x128 tile, BK=16, 256 threads, warp tile 64x32.
// EPI=1: scatter into q/k/v seq layout (+ NHWC V copy).
// ============================================================
#define TLD 136

__device__ __forceinline__ unsigned f2tf32(float x)
{
    unsigned r;
    asm("cvt.rna.tf32.f32 %0, %1;" : "=r"(r) : "f"(x));
    return r;
}

#define MMA_TF32(c, a, b) asm volatile( \
    "mma.sync.aligned.m16n8k8.row.col.f32.tf32.tf32.f32 " \
    "{%0,%1,%2,%3},{%4,%5,%6,%7},{%8,%9},{%0,%1,%2,%3};" \
    : "+f"(c[0]), "+f"(c[1]), "+f"(c[2]), "+f"(c[3]) \
    : "r"(a[0]), "r"(a[1]), "r"(a[2]), "r"(a[3]), "r"(b[0]), "r"(b[1]))

template<int EPI, int TERMS>
__global__ __launch_bounds__(256)
void tf32_gemm(const float* __restrict__ A, const float* __restrict__ W,
               const float* __restrict__ bias, float* __restrict__ Cm,
               int Nd, int n_base)
{
    constexpr int NP = (TERMS == 6) ? 3 : 2;
    constexpr int PL = 16 * TLD;                // one plane (one k-slab)
    extern __shared__ __align__(16) unsigned smem_u[];
    unsigned* Abase = smem_u;                   // [NP][2][PL]
    unsigned* Wbase = smem_u + NP * 2 * PL;
    float* Cs = (float*)smem_u;                 // reuse: [128][132]

    const int tid = threadIdx.x;
    const int warp = tid >> 5, lane = tid & 31;
    const int wm = (warp >> 2) * 64, wn = (warp & 3) * 32;
    const int m0 = blockIdx.y * 128;
    const int n0 = n_base + blockIdx.x * 128;
    const int qrow = lane >> 2, qk = lane & 3;

    float c[4][4][4];
#pragma unroll
    for (int mt = 0; mt < 4; mt++)
#pragma unroll
        for (int nt = 0; nt < 4; nt++)
#pragma unroll
            for (int i = 0; i < 4; i++) c[mt][nt][i] = 0.f;

    auto stage = [&](int kt, int buf) {
#pragma unroll
        for (int i = 0; i < 2; i++) {
            int idx = tid + i * 256;               // 0..511
            int row = idx >> 2, kseg = (idx & 3) * 4;
            float4 a = *(const float4*)&A[(size_t)(m0 + row) * 256 + kt * 16 + kseg];
            float4 w = *(const float4*)&W[(size_t)(n0 + row) * 256 + kt * 16 + kseg];
            float av[4] = {a.x, a.y, a.z, a.w};
            float wv[4] = {w.x, w.y, w.z, w.w};
#pragma unroll
            for (int q = 0; q < 4; q++) {
                int off = buf * PL + (kseg + q) * TLD + row;
                {
                    float x = av[q];
                    unsigned h = f2tf32(x);
                    float r1 = x - __uint_as_float(h);
                    Abase[0 * 2 * PL + off] = h;
                    if (NP == 2) {
                        Abase[1 * 2 * PL + off] = f2tf32(r1);
                    } else {
                        unsigned mm_ = f2tf32(r1);
                        float r2 = r1 - __uint_as_float(mm_);
                        Abase[1 * 2 * PL + off] = mm_;
                        Abase[2 * 2 * PL + off] = f2tf32(r2);
                    }
                }
                {
                    float x = wv[q];
                    unsigned h = f2tf32(x);
                    float r1 = x - __uint_as_float(h);
                    Wbase[0 * 2 * PL + off] = h;
                    if (NP == 2) {
                        Wbase[1 * 2 * PL + off] = f2tf32(r1);
                    } else {
                        unsigned mm_ = f2tf32(r1);
                        float r2 = r1 - __uint_as_float(mm_);
                        Wbase[1 * 2 * PL + off] = mm_;
                        Wbase[2 * 2 * PL + off] = f2tf32(r2);
                    }
                }
            }
        }
    };

    auto compute = [&](int buf) {
#pragma unroll
        for (int ch = 0; ch < 2; ch++) {
            const int kc = ch * 8 + qk;
#pragma unroll
            for (int pa = 0; pa < NP; pa++) {
                const unsigned* ap = Abase + pa * 2 * PL + buf * PL;
                unsigned afr[4][4];
#pragma unroll
                for (int mt = 0; mt < 4; mt++) {
                    int r0 = wm + mt * 16 + qrow;
                    afr[mt][0] = ap[kc * TLD + r0];
                    afr[mt][1] = ap[kc * TLD + r0 + 8];
                    afr[mt][2] = ap[(kc + 4) * TLD + r0];
                    afr[mt][3] = ap[(kc + 4) * TLD + r0 + 8];
                }
#pragma unroll
                for (int pb = 0; pb < NP; pb++) {
                    if (pa + pb >= NP) continue;   // hh + cross terms only
                    const unsigned* wp = Wbase + pb * 2 * PL + buf * PL;
                    unsigned bfr[4][2];
#pragma unroll
                    for (int nt = 0; nt < 4; nt++) {
                        int r0 = wn + nt * 8 + qrow;
                        bfr[nt][0] = wp[kc * TLD + r0];
                        bfr[nt][1] = wp[(kc + 4) * TLD + r0];
                    }
#pragma unroll
                    for (int mt = 0; mt < 4; mt++)
#pragma unroll
                        for (int nt = 0; nt < 4; nt++)
                            MMA_TF32(c[mt][nt], afr[mt], bfr[nt]);
                }
            }
        }
    };

    stage(0, 0);
    __syncthreads();
#pragma unroll 1
    for (int kt = 0; kt < 16; kt++) {
        const int cur = kt & 1;
        compute(cur);
        if (kt + 1 < 16) stage(kt + 1, cur ^ 1);
        __syncthreads();
    }

    // frags -> smem (fp32) -> coalesced epilogue
#pragma unroll
    for (int mt = 0; mt < 4; mt++)
#pragma unroll
        for (int nt = 0; nt < 4; nt++) {
            int row = wm + mt * 16 + qrow;
            int col = wn + nt * 8 + 2 * qk;
            Cs[row * 132 + col]           = c[mt][nt][0];
            Cs[row * 132 + col + 1]       = c[mt][nt][1];
            Cs[(row + 8) * 132 + col]     = c[mt][nt][2];
            Cs[(row + 8) * 132 + col + 1] = c[mt][nt][3];
        }
    __syncthreads();

#pragma unroll 1
    for (int j = 0; j < 16; j++) {
        int f4 = tid + j * 256;
        int row = f4 >> 5, c4 = (f4 & 31) * 4;
        float4 v = *(float4*)&Cs[row * 132 + c4];
        int n = n0 + c4;
        float4 bn = *(const float4*)&bias[n];
        v.x += bn.x; v.y += bn.y; v.z += bn.z; v.w += bn.w;
        int m = m0 + row;
        if (EPI == 0) {
            *(float4*)&Cm[(size_t)m * Nd + n] = v;
        } else {
            int b = m / 3136;
            int hw = m - b * 3136;
            int h = hw / 56, w = hw - (hw / 56) * 56;
            int r = (h >> 3) * 7 + (w >> 3);
            int s = ((h & 7) << 3) + (w & 7);
            int t = n >> 8;
            int cch = n & 255;
            int head = cch >> 5, d = cch & 31;
            float* dstb = (t == 0) ? g_qseq : (t == 1) ? g_kseq : g_vseq;
            size_t dst = ((((size_t)(b * 8 + head) * 49 + r) * 64 + s) * 32 + d);
            *(float4*)&dstb[dst] = v;
            if (t == 2) *(float4*)&g_vhwc[(size_t)m * 256 + cch] = v;
        }
    }
}

// ============================================================
// bf16x3 tensor-core GEMM (output projection only)
// ============================================================
#define LDK 40

#define MMA_BF16(c, a, b) asm volatile( \
    "mma.sync.aligned.m16n8k16.row.col.f32.bf16.bf16.f32 " \
    "{%0,%1,%2,%3},{%4,%5,%6,%7},{%8,%9},{%0,%1,%2,%3};" \
    : "+f"(c[0]), "+f"(c[1]), "+f"(c[2]), "+f"(c[3]) \
    : "r"(a[0]), "r"(a[1]), "r"(a[2]), "r"(a[3]), "r"(b[0]), "r"(b[1]))

__device__ __forceinline__ void split_store(__nv_bfloat16* dh, __nv_bfloat16* dl, float4 a)
{
    __nv_bfloat16 h0 = __float2bfloat16(a.x);
    __nv_bfloat16 h1 = __float2bfloat16(a.y);
    __nv_bfloat16 h2 = __float2bfloat16(a.z);
    __nv_bfloat16 h3 = __float2bfloat16(a.w);
    float l0 = a.x - __bfloat162float(h0);
    float l1 = a.y - __bfloat162float(h1);
    float l2 = a.z - __bfloat162float(h2);
    float l3 = a.w - __bfloat162float(h3);
    ((__nv_bfloat162*)dh)[0] = __halves2bfloat162(h0, h1);
    ((__nv_bfloat162*)dh)[1] = __halves2bfloat162(h2, h3);
    ((__nv_bfloat162*)dl)[0] = __floats2bfloat162_rn(l0, l1);
    ((__nv_bfloat162*)dl)[1] = __floats2bfloat162_rn(l2, l3);
}

__global__ __launch_bounds__(256)
void bf16_gemm(const float* __restrict__ A, const float* __restrict__ W,
               const float* __restrict__ bias, float* __restrict__ Cm, int Nd)
{
    extern __shared__ __align__(16) char smem_raw[];
    __nv_bfloat16* Ah = (__nv_bfloat16*)smem_raw;
    __nv_bfloat16* Al = Ah + 2 * 128 * LDK;
    __nv_bfloat16* Wh = Al + 2 * 128 * LDK;
    __nv_bfloat16* Wl = Wh + 2 * 128 * LDK;
    float* Cs = (float*)smem_raw;

    const int tid = threadIdx.x;
    const int warp = tid >> 5, lane = tid & 31;
    const int wm = (warp >> 2) * 64, wn = (warp & 3) * 32;
    const int m0 = blockIdx.y * 128, n0 = blockIdx.x * 128;

    float c[4][4][4];
#pragma unroll
    for (int mt = 0; mt < 4; mt++)
#pragma unroll
        for (int nt = 0; nt < 4; nt++)
#pragma unroll
            for (int i = 0; i < 4; i++) c[mt][nt][i] = 0.f;

    auto stage = [&](int kt, int buf) {
#pragma unroll
        for (int i = 0; i < 4; i++) {
            int idx = tid + i * 256;
            int row = idx >> 3, seg = (idx & 7) * 4;
            float4 a = *(const float4*)&A[(size_t)(m0 + row) * 256 + kt * 32 + seg];
            float4 w = *(const float4*)&W[(size_t)(n0 + row) * 256 + kt * 32 + seg];
            split_store(Ah + buf * 128 * LDK + row * LDK + seg,
                        Al + buf * 128 * LDK + row * LDK + seg, a);
            split_store(Wh + buf * 128 * LDK + row * LDK + seg,
                        Wl + buf * 128 * LDK + row * LDK + seg, w);
        }
    };

    auto compute = [&](int buf) {
        const __nv_bfloat16* Abh = Ah + buf * 128 * LDK;
        const __nv_bfloat16* Abl = Al + buf * 128 * LDK;
        const __nv_bfloat16* Wbh = Wh + buf * 128 * LDK;
        const __nv_bfloat16* Wbl = Wl + buf * 128 * LDK;
#pragma unroll
        for (int ks = 0; ks < 2; ks++) {
            const int kc = ks * 16 + 2 * (lane & 3);
            unsigned ah[4][4], al[4][4], bh[4][2], bl[4][2];
#pragma unroll
            for (int mt = 0; mt < 4; mt++) {
                int r0 = wm + mt * 16 + (lane >> 2);
                ah[mt][0] = *(const unsigned*)&Abh[r0 * LDK + kc];
                ah[mt][1] = *(const unsigned*)&Abh[(r0 + 8) * LDK + kc];
                ah[mt][2] = *(const unsigned*)&Abh[r0 * LDK + kc + 8];
                ah[mt][3] = *(const unsigned*)&Abh[(r0 + 8) * LDK + kc + 8];
                al[mt][0] = *(const unsigned*)&Abl[r0 * LDK + kc];
                al[mt][1] = *(const unsigned*)&Abl[(r0 + 8) * LDK + kc];
                al[mt][2] = *(const unsigned*)&Abl[r0 * LDK + kc + 8];
                al[mt][3] = *(const unsigned*)&Abl[(r0 + 8) * LDK + kc + 8];
            }
#pragma unroll
            for (int nt = 0; nt < 4; nt++) {
                int r0 = wn + nt * 8 + (lane >> 2);
                bh[nt][0] = *(const unsigned*)&Wbh[r0 * LDK + kc];
                bh[nt][1] = *(const unsigned*)&Wbh[r0 * LDK + kc + 8];
                bl[nt][0] = *(const unsigned*)&Wbl[r0 * LDK + kc];
                bl[nt][1] = *(const unsigned*)&Wbl[r0 * LDK + kc + 8];
            }
#pragma unroll
            for (int mt = 0; mt < 4; mt++)
#pragma unroll
                for (int nt = 0; nt < 4; nt++) {
                    MMA_BF16(c[mt][nt], ah[mt], bh[nt]);
                    MMA_BF16(c[mt][nt], ah[mt], bl[nt]);
                    MMA_BF16(c[mt][nt], al[mt], bh[nt]);
                }
        }
    };

    stage(0, 0);
    __syncthreads();
#pragma unroll 1
    for (int kt = 0; kt < 8; kt++) {
        const int cur = kt & 1;
        compute(cur);
        if (kt + 1 < 8) stage(kt + 1, cur ^ 1);
        __syncthreads();
    }

#pragma unroll
    for (int mt = 0; mt < 4; mt++)
#pragma unroll
        for (int nt = 0; nt < 4; nt++) {
            int row = wm + mt * 16 + (lane >> 2);
            int col = wn + nt * 8 + 2 * (lane & 3);
            Cs[row * 132 + col]           = c[mt][nt][0];
            Cs[row * 132 + col + 1]       = c[mt][nt][1];
            Cs[(row + 8) * 132 + col]     = c[mt][nt][2];
            Cs[(row + 8) * 132 + col + 1] = c[mt][nt][3];
        }
    __syncthreads();

#pragma unroll 1
    for (int j = 0; j < 16; j++) {
        int f4 = tid + j * 256;
        int row = f4 >> 5, c4 = (f4 & 31) * 4;
        float4 v = *(float4*)&Cs[row * 132 + c4];
        int n = n0 + c4;
        float4 bn = *(const float4*)&bias[n];
        v.x += bn.x; v.y += bn.y; v.z += bn.z; v.w += bn.w;
        int m = m0 + row;
        *(float4*)&Cm[(size_t)m * Nd + n] = v;
    }
}

// ---------------- region pooling ----------------
__global__ void pool_kernel()
{
    int i = blockIdx.x * 256 + threadIdx.x;
    if (i >= BB * NREG * CC) return;
    int c = i & 255;
    int r = (i >> 8) % 49;
    int b = i / (256 * 49);
    int head = c >> 5, d = c & 31;
    int base = (((b * NHD + head) * NREG + r) * SS) * HD + d;
    float sq = 0.f, sk = 0.f;
#pragma unroll 8
    for (int s = 0; s < SS; s++) {
        sq += g_qseq[base + s * HD];
        sk += g_kseq[base + s * HD];
    }
    g_qr[i] = sq * (1.f / 64.f);
    g_kr[i] = sk * (1.f / 64.f);
}

// ---------------- region routing top-4 ----------------
__global__ void region_topk_kernel()
{
    extern __shared__ float rsm[];
    float* kr = rsm;
    float* qv = rsm + 49 * 257;
    __shared__ float a[64];

    int bn = blockIdx.x;
    int b = bn / NREG, nq = bn % NREG;
    int tid = threadIdx.x;

    const float* src = &g_kr[(size_t)b * NREG * CC];
    for (int i = tid; i < NREG * CC; i += 256) {
        int t = i >> 8, c = i & 255;
        kr[t * 257 + c] = src[i];
    }
    const float* qsrc = &g_qr[((size_t)b * NREG + nq) * CC];
    if (tid < CC) qv[tid] = qsrc[tid];
    __syncthreads();

    if (tid < NREG) {
        float accv = 0.f;
#pragma unroll 8
        for (int c = 0; c < CC; c++) accv += qv[c] * kr[tid * 257 + c];
        a[tid] = accv;
    }
    __syncthreads();
    if (tid == 0) {
        for (int t = 0; t < TOPKR; t++) {
            float bm = -INFINITY; int bi = 0;
            for (int m = 0; m < NREG; m++)
                if (a[m] > bm) { bm = a[m]; bi = m; }
            g_idx[(b * NREG + nq) * TOPKR + t] = bi;
            a[bi] = -INFINITY;
        }
    }
}

// ---------------- fused attention ----------------
// threshold-based top-32: binary search on orderable uints -> exact set,
// ballot-scan compaction, broadcast V gather. 3 CTAs/SM.
__global__ __launch_bounds__(256, 3)
void attn_kernel()
{
    extern __shared__ __align__(16) float asm_[];
    float* Qs = asm_;                         // [64][32]
    float* Kg = Qs + 64 * 32;                 // [256][32] xor-swizzled groups
    float* Vg = Kg + 256 * 32;                // [256][32]
    float2* buf = (float2*)(Vg + 256 * 32);   // [8 warps][32]

    int bid = blockIdx.x;
    int n = bid % NREG;
    int head = (bid / NREG) & 7;
    int b = bid / (NREG * NHD);
    int tid = threadIdx.x;
    int warp = tid >> 5, lane = tid & 31;
    const unsigned FULL = 0xffffffffu;

    {
        const float4* src = (const float4*)&g_qseq[(((size_t)(b * NHD + head) * NREG + n) * SS) * HD];
        for (int i4 = tid; i4 < 512; i4 += 256) {
            int row = i4 >> 3, g = i4 & 7;
            *(float4*)&Qs[row * 32 + g * 4] = src[i4];
        }
    }
    for (int t = 0; t < TOPKR; t++) {
        int rt = g_idx[(b * NREG + n) * TOPKR + t];
        const float4* ks = (const float4*)&g_kseq[(((size_t)(b * NHD + head) * NREG + rt) * SS) * HD];
        const float4* vs = (const float4*)&g_vseq[(((size_t)(b * NHD + head) * NREG + rt) * SS) * HD];
        for (int i4 = tid; i4 < 512; i4 += 256) {
            int lrow = i4 >> 3, g = i4 & 7;
            int row = t * 64 + lrow;
            *(float4*)&Kg[row * 32 + ((g ^ (row & 7)) << 2)] = ks[i4];
            *(float4*)&Vg[row * 32 + g * 4] = vs[i4];
        }
    }
    __syncthreads();

    float2* mybuf = (float2*)buf + warp * 32;

#pragma unroll 1
    for (int half = 0; half < 2; half++) {
        int rbase = warp * 8 + half * 4;
        float acc[4][8];
#pragma unroll
        for (int r = 0; r < 4; r++)
#pragma unroll
            for (int j = 0; j < 8; j++) acc[r][j] = 0.f;

#pragma unroll
        for (int g = 0; g < 8; g++) {
            int gsw = ((g ^ (lane & 7)) << 2);
            float4 qv[4];
#pragma unroll
            for (int r = 0; r < 4; r++) qv[r] = *(const float4*)&Qs[(rbase + r) * 32 + g * 4];
#pragma unroll
            for (int jh = 0; jh < 2; jh++) {
                float4 kv[4];
#pragma unroll
                for (int jj = 0; jj < 4; jj++)
                    kv[jj] = *(const float4*)&Kg[(lane + 32 * (jh * 4 + jj)) * 32 + gsw];
#pragma unroll
                for (int r = 0; r < 4; r++)
#pragma unroll
                    for (int jj = 0; jj < 4; jj++) {
                        acc[r][jh * 4 + jj] += qv[r].x * kv[jj].x;
                        acc[r][jh * 4 + jj] += qv[r].y * kv[jj].y;
                        acc[r][jh * 4 + jj] += qv[r].z * kv[jj].z;
                        acc[r][jh * 4 + jj] += qv[r].w * kv[jj].w;
                    }
            }
        }

#pragma unroll 1
        for (int r = 0; r < 4; r++) {
            unsigned u[8];
#pragma unroll
            for (int j = 0; j < 8; j++) {
                unsigned bts = __float_as_uint(acc[r][j]);
                u[j] = (bts & 0x80000000u) ? ~bts : (bts | 0x80000000u);
            }
            unsigned mx8 = u[0], mn8 = u[0];
#pragma unroll
            for (int j = 1; j < 8; j++) {
                mx8 = (u[j] > mx8) ? u[j] : mx8;
                mn8 = (u[j] < mn8) ? u[j] : mn8;
            }
            unsigned hi = __reduce_max_sync(FULL, mx8);
            unsigned lo = __reduce_min_sync(FULL, mn8) - 1u;
            float mxf = (hi & 0x80000000u) ? __uint_as_float(hi ^ 0x80000000u)
                                           : __uint_as_float(~hi);
            unsigned thr = hi;
            int found = 0;
            while (hi - lo > 1u) {
                unsigned t = lo + ((hi - lo) >> 1);
                int c = 0;
#pragma unroll
                for (int j = 0; j < 8; j++) c += (u[j] > t) ? 1 : 0;
                c = __reduce_add_sync(FULL, c);
                if (c == 32) { thr = t; found = 1; break; }
                if (c > 32) lo = t; else hi = t;
            }
            unsigned selmask = 0;
            if (found) {
#pragma unroll
                for (int j = 0; j < 8; j++)
                    if (u[j] > thr) selmask |= (1u << j);
            } else {
                // boundary duplicates: take u>hi, then u==hi by lowest global index
                int cg = 0;
#pragma unroll
                for (int j = 0; j < 8; j++) cg += (u[j] > hi) ? 1 : 0;
                int need = 32 - __reduce_add_sync(FULL, cg);
                int taken = 0;
#pragma unroll
                for (int j = 0; j < 8; j++) {
                    bool eq = (u[j] == hi);
                    unsigned bm = __ballot_sync(FULL, eq);
                    int before = taken + __popc(bm & ((1u << lane) - 1u));
                    if ((u[j] > hi) || (eq && before < need)) selmask |= (1u << j);
                    taken += __popc(bm);
                }
            }
            int cnt = __popc(selmask);
            int pos = cnt;
#pragma unroll
            for (int off = 1; off < 32; off <<= 1) {
                int nb = __shfl_up_sync(FULL, pos, off);
                if (lane >= off) pos += nb;
            }
            pos -= cnt;
#pragma unroll
            for (int j = 0; j < 8; j++) {
                if ((selmask >> j) & 1u) {
                    mybuf[pos] = make_float2(acc[r][j], __int_as_float(lane + 32 * j));
                    pos++;
                }
            }
            __syncwarp();
            float2 ent = mybuf[lane];      // exactly 32 selected -> all valid
            float e = __expf((ent.x - mxf) * SCALE);
            float s = e;
#pragma unroll
            for (int off = 16; off; off >>= 1) s += __shfl_xor_sync(FULL, s, off);
            float wgt = e / s;
            int myid = __float_as_int(ent.y);
            float outv = 0.f;
#pragma unroll
            for (int k = 0; k < 32; k++) {
                float wk = __shfl_sync(FULL, wgt, k);
                int ik = __shfl_sync(FULL, myid, k);
                outv += wk * Vg[ik * 32 + lane];
            }
            int row = rbase + r;
            int hh = (n / 7) * 8 + (row >> 3);
            int ww = (n % 7) * 8 + (row & 7);
            int m = b * 3136 + hh * 56 + ww;
            g_attn_out[(size_t)m * CC + head * HD + lane] = outv;
            __syncwarp();
        }
    }
}

// ---------------- lepe (reads NHWC V copy, coalesced) ----------------
__global__ void lepe_kernel(const float* __restrict__ lepe_w, const float* __restrict__ lepe_b)
{
    int idx = blockIdx.x * 256 + threadIdx.x;
    int c = idx & 255;
    int m = idx >> 8;
    int b = m / (HH * WW);
    int hw = m % (HH * WW);
    int h = hw / WW, w = hw % WW;

    float acc = lepe_b[c];
#pragma unroll
    for (int i = 0; i < 3; i++) {
        int hh = h + i - 1;
        if (hh < 0 || hh >= HH) continue;
#pragma unroll
        for (int j = 0; j < 3; j++) {
            int ww = w + j - 1;
            if (ww < 0 || ww >= WW) continue;
            float vv = g_vhwc[((size_t)(b * 3136) + hh * 56 + ww) * 256 + c];
            acc += vv * lepe_w[c * 9 + i * 3 + j];
        }
    }
    g_attn_out[idx] += acc;
}

// ---------------- launch ----------------
extern "C" void kernel_launch(void* const* d_in, const int* in_sizes, int n_in,
                              void* d_out, int out_size)
{
    const float* x      = (const float*)d_in[0];
    const float* qkv_w  = (const float*)d_in[1];
    const float* qkv_b  = (const float*)d_in[2];
    const float* lepe_w = (const float*)d_in[3];
    const float* lepe_b = (const float*)d_in[4];
    const float* out_w  = (const float*)d_in[5];
    const float* out_b  = (const float*)d_in[6];
    float* out = (float*)d_out;

    float* attn_buf = nullptr;
    cudaGetSymbolAddress((void**)&attn_buf, g_attn_out);

    const int tf32_smem6 = 6 * 2 * 16 * TLD * 4;   // 104448
    const int tf32_smem3 = 4 * 2 * 16 * TLD * 4;   // 69632
    const int bf16_smem  = 2 * 128 * LDK * 4 * (int)sizeof(__nv_bfloat16);  // 81920
    const int attn_smem  = (64 * 32 + 2 * 256 * 32) * 4 + 8 * 32 * 8;       // 75776

    cudaFuncSetAttribute(tf32_gemm<1, 6>, cudaFuncAttributeMaxDynamicSharedMemorySize, tf32_smem6);
    cudaFuncSetAttribute(tf32_gemm<1, 3>, cudaFuncAttributeMaxDynamicSharedMemorySize, tf32_smem3);
    cudaFuncSetAttribute(bf16_gemm, cudaFuncAttributeMaxDynamicSharedMemorySize, bf16_smem);
    cudaFuncSetAttribute(attn_kernel, cudaFuncAttributeMaxDynamicSharedMemorySize, attn_smem);

    // 1a) Q,K columns: fp32-faithful 3-split tf32 (selection-critical)
    tf32_gemm<1, 6><<<dim3(4, MM / 128), 256, tf32_smem6>>>(x, qkv_w, qkv_b, nullptr, 768, 0);
    // 1b) V columns: 2-split tf32 (linear path)
    tf32_gemm<1, 3><<<dim3(2, MM / 128), 256, tf32_smem3>>>(x, qkv_w, qkv_b, nullptr, 768, 512);

    // 2) region pooling
    pool_kernel<<<(BB * NREG * CC + 255) / 256, 256>>>();

    // 3) region routing top-4
    {
        int smem = (49 * 257 + 256) * (int)sizeof(float);
        cudaFuncSetAttribute(region_topk_kernel, cudaFuncAttributeMaxDynamicSharedMemorySize, smem);
        region_topk_kernel<<<BB * NREG, 256, smem>>>();
    }

    // 4) fused attention (threshold top-32)
    attn_kernel<<<BB * NHD * NREG, 256, attn_smem>>>();

    // 5) lepe
    lepe_kernel<<<(MM * CC) / 256, 256>>>(lepe_w, lepe_b);

    // 6) output projection (bf16x3)
    bf16_gemm<<<dim3(CC / 128, MM / 128), 256, bf16_smem>>>(attn_buf, out_w, out_b, out, 256);
}

// round 6
// speedup vs baseline: 3.8580x; 1.3021x over previous
#include <cuda_runtime.h>
#include <cuda_bf16.h>
#include <math.h>

// ---------------- problem constants ----------------
#define BB    8
#define HH    56
#define WW    56
#define CC    256
#define MM    (BB*HH*WW)       // 25088
#define NHD   8
#define HD    32
#define NWIN  7
#define NREG  49
#define SS    64
#define TOPKR 4
#define TS    256
#define K2    32
#define SCALE 0.0625f

// ---------------- scratch ----------------
__device__ float  g_qseq[BB*NHD*NREG*SS*HD];
__device__ float  g_kseq[BB*NHD*NREG*SS*HD];
__device__ float  g_vseq[BB*NHD*NREG*SS*HD];
__device__ float  g_vhwc[MM*CC];
__device__ double g_qr[BB*NREG*CC];
__device__ double g_kr[BB*NREG*CC];
__device__ int    g_idx[BB*NREG*TOPKR];
__device__ float  g_attn_out[MM*CC];

// ============================================================
// TF32 2-split tensor-core GEMM: C = A @ W^T + bias  (3 MMA terms: hh,hl,lh)
// 128x128 tile, BK=16, 256 threads, warp tile 64x32.
// EPI=1: scatter into q/k/v seq layout (+ NHWC V copy).
// ============================================================
#define TLD 136

__device__ __forceinline__ unsigned f2tf32(float x)
{
    unsigned r;
    asm("cvt.rna.tf32.f32 %0, %1;" : "=r"(r) : "f"(x));
    return r;
}

#define MMA_TF32(c, a, b) asm volatile( \
    "mma.sync.aligned.m16n8k8.row.col.f32.tf32.tf32.f32 " \
    "{%0,%1,%2,%3},{%4,%5,%6,%7},{%8,%9},{%0,%1,%2,%3};" \
    : "+f"(c[0]), "+f"(c[1]), "+f"(c[2]), "+f"(c[3]) \
    : "r"(a[0]), "r"(a[1]), "r"(a[2]), "r"(a[3]), "r"(b[0]), "r"(b[1]))

template<int EPI>
__global__ __launch_bounds__(256)
void tf32_gemm(const float* __restrict__ A, const float* __restrict__ W,
               const float* __restrict__ bias, float* __restrict__ Cm,
               int Nd, int n_base)
{
    constexpr int NP = 2;
    constexpr int PL = 16 * TLD;
    extern __shared__ __align__(16) unsigned smem_u[];
    unsigned* Abase = smem_u;                   // [NP][2][PL]
    unsigned* Wbase = smem_u + NP * 2 * PL;
    float* Cs = (float*)smem_u;                 // reuse: [128][132]

    const int tid = threadIdx.x;
    const int warp = tid >> 5, lane = tid & 31;
    const int wm = (warp >> 2) * 64, wn = (warp & 3) * 32;
    const int m0 = blockIdx.y * 128;
    const int n0 = n_base + blockIdx.x * 128;
    const int qrow = lane >> 2, qk = lane & 3;

    float c[4][4][4];
#pragma unroll
    for (int mt = 0; mt < 4; mt++)
#pragma unroll
        for (int nt = 0; nt < 4; nt++)
#pragma unroll
            for (int i = 0; i < 4; i++) c[mt][nt][i] = 0.f;

    auto stage = [&](int kt, int buf) {
#pragma unroll
        for (int i = 0; i < 2; i++) {
            int idx = tid + i * 256;
            int row = idx >> 2, kseg = (idx & 3) * 4;
            float4 a = *(const float4*)&A[(size_t)(m0 + row) * 256 + kt * 16 + kseg];
            float4 w = *(const float4*)&W[(size_t)(n0 + row) * 256 + kt * 16 + kseg];
            float av[4] = {a.x, a.y, a.z, a.w};
            float wv[4] = {w.x, w.y, w.z, w.w};
#pragma unroll
            for (int q = 0; q < 4; q++) {
                int off = buf * PL + (kseg + q) * TLD + row;
                unsigned h = f2tf32(av[q]);
                Abase[off] = h;
                Abase[2 * PL + off] = f2tf32(av[q] - __uint_as_float(h));
                unsigned wh = f2tf32(wv[q]);
                Wbase[off] = wh;
                Wbase[2 * PL + off] = f2tf32(wv[q] - __uint_as_float(wh));
            }
        }
    };

    auto compute = [&](int buf) {
#pragma unroll
        for (int ch = 0; ch < 2; ch++) {
            const int kc = ch * 8 + qk;
#pragma unroll
            for (int pa = 0; pa < NP; pa++) {
                const unsigned* ap = Abase + pa * 2 * PL + buf * PL;
                unsigned afr[4][4];
#pragma unroll
                for (int mt = 0; mt < 4; mt++) {
                    int r0 = wm + mt * 16 + qrow;
                    afr[mt][0] = ap[kc * TLD + r0];
                    afr[mt][1] = ap[kc * TLD + r0 + 8];
                    afr[mt][2] = ap[(kc + 4) * TLD + r0];
                    afr[mt][3] = ap[(kc + 4) * TLD + r0 + 8];
                }
#pragma unroll
                for (int pb = 0; pb < NP; pb++) {
                    if (pa + pb >= NP) continue;   // hh, hl, lh
                    const unsigned* wp = Wbase + pb * 2 * PL + buf * PL;
                    unsigned bfr[4][2];
#pragma unroll
                    for (int nt = 0; nt < 4; nt++) {
                        int r0 = wn + nt * 8 + qrow;
                        bfr[nt][0] = wp[kc * TLD + r0];
                        bfr[nt][1] = wp[(kc + 4) * TLD + r0];
                    }
#pragma unroll
                    for (int mt = 0; mt < 4; mt++)
#pragma unroll
                        for (int nt = 0; nt < 4; nt++)
                            MMA_TF32(c[mt][nt], afr[mt], bfr[nt]);
                }
            }
        }
    };

    stage(0, 0);
    __syncthreads();
#pragma unroll 1
    for (int kt = 0; kt < 16; kt++) {
        const int cur = kt & 1;
        compute(cur);
        if (kt + 1 < 16) stage(kt + 1, cur ^ 1);
        __syncthreads();
    }

#pragma unroll
    for (int mt = 0; mt < 4; mt++)
#pragma unroll
        for (int nt = 0; nt < 4; nt++) {
            int row = wm + mt * 16 + qrow;
            int col = wn + nt * 8 + 2 * qk;
            Cs[row * 132 + col]           = c[mt][nt][0];
            Cs[row * 132 + col + 1]       = c[mt][nt][1];
            Cs[(row + 8) * 132 + col]     = c[mt][nt][2];
            Cs[(row + 8) * 132 + col + 1] = c[mt][nt][3];
        }
    __syncthreads();

#pragma unroll 1
    for (int j = 0; j < 16; j++) {
        int f4 = tid + j * 256;
        int row = f4 >> 5, c4 = (f4 & 31) * 4;
        float4 v = *(float4*)&Cs[row * 132 + c4];
        int n = n0 + c4;
        float4 bn = *(const float4*)&bias[n];
        v.x += bn.x; v.y += bn.y; v.z += bn.z; v.w += bn.w;
        int m = m0 + row;
        if (EPI == 0) {
            *(float4*)&Cm[(size_t)m * Nd + n] = v;
        } else {
            int b = m / 3136;
            int hw = m - b * 3136;
            int h = hw / 56, w = hw - (hw / 56) * 56;
            int r = (h >> 3) * 7 + (w >> 3);
            int s = ((h & 7) << 3) + (w & 7);
            int t = n >> 8;
            int cch = n & 255;
            int head = cch >> 5, d = cch & 31;
            float* dstb = (t == 0) ? g_qseq : (t == 1) ? g_kseq : g_vseq;
            size_t dst = ((((size_t)(b * 8 + head) * 49 + r) * 64 + s) * 32 + d);
            *(float4*)&dstb[dst] = v;
            if (t == 2) *(float4*)&g_vhwc[(size_t)m * 256 + cch] = v;
        }
    }
}

// ============================================================
// bf16x3 tensor-core GEMM (output projection only)
// ============================================================
#define LDK 40

#define MMA_BF16(c, a, b) asm volatile( \
    "mma.sync.aligned.m16n8k16.row.col.f32.bf16.bf16.f32 " \
    "{%0,%1,%2,%3},{%4,%5,%6,%7},{%8,%9},{%0,%1,%2,%3};" \
    : "+f"(c[0]), "+f"(c[1]), "+f"(c[2]), "+f"(c[3]) \
    : "r"(a[0]), "r"(a[1]), "r"(a[2]), "r"(a[3]), "r"(b[0]), "r"(b[1]))

__device__ __forceinline__ void split_store(__nv_bfloat16* dh, __nv_bfloat16* dl, float4 a)
{
    __nv_bfloat16 h0 = __float2bfloat16(a.x);
    __nv_bfloat16 h1 = __float2bfloat16(a.y);
    __nv_bfloat16 h2 = __float2bfloat16(a.z);
    __nv_bfloat16 h3 = __float2bfloat16(a.w);
    float l0 = a.x - __bfloat162float(h0);
    float l1 = a.y - __bfloat162float(h1);
    float l2 = a.z - __bfloat162float(h2);
    float l3 = a.w - __bfloat162float(h3);
    ((__nv_bfloat162*)dh)[0] = __halves2bfloat162(h0, h1);
    ((__nv_bfloat162*)dh)[1] = __halves2bfloat162(h2, h3);
    ((__nv_bfloat162*)dl)[0] = __floats2bfloat162_rn(l0, l1);
    ((__nv_bfloat162*)dl)[1] = __floats2bfloat162_rn(l2, l3);
}

__global__ __launch_bounds__(256)
void bf16_gemm(const float* __restrict__ A, const float* __restrict__ W,
               const float* __restrict__ bias, float* __restrict__ Cm, int Nd)
{
    extern __shared__ __align__(16) char smem_raw[];
    __nv_bfloat16* Ah = (__nv_bfloat16*)smem_raw;
    __nv_bfloat16* Al = Ah + 2 * 128 * LDK;
    __nv_bfloat16* Wh = Al + 2 * 128 * LDK;
    __nv_bfloat16* Wl = Wh + 2 * 128 * LDK;
    float* Cs = (float*)smem_raw;

    const int tid = threadIdx.x;
    const int warp = tid >> 5, lane = tid & 31;
    const int wm = (warp >> 2) * 64, wn = (warp & 3) * 32;
    const int m0 = blockIdx.y * 128, n0 = blockIdx.x * 128;

    float c[4][4][4];
#pragma unroll
    for (int mt = 0; mt < 4; mt++)
#pragma unroll
        for (int nt = 0; nt < 4; nt++)
#pragma unroll
            for (int i = 0; i < 4; i++) c[mt][nt][i] = 0.f;

    auto stage = [&](int kt, int buf) {
#pragma unroll
        for (int i = 0; i < 4; i++) {
            int idx = tid + i * 256;
            int row = idx >> 3, seg = (idx & 7) * 4;
            float4 a = *(const float4*)&A[(size_t)(m0 + row) * 256 + kt * 32 + seg];
            float4 w = *(const float4*)&W[(size_t)(n0 + row) * 256 + kt * 32 + seg];
            split_store(Ah + buf * 128 * LDK + row * LDK + seg,
                        Al + buf * 128 * LDK + row * LDK + seg, a);
            split_store(Wh + buf * 128 * LDK + row * LDK + seg,
                        Wl + buf * 128 * LDK + row * LDK + seg, w);
        }
    };

    auto compute = [&](int buf) {
        const __nv_bfloat16* Abh = Ah + buf * 128 * LDK;
        const __nv_bfloat16* Abl = Al + buf * 128 * LDK;
        const __nv_bfloat16* Wbh = Wh + buf * 128 * LDK;
        const __nv_bfloat16* Wbl = Wl + buf * 128 * LDK;
#pragma unroll
        for (int ks = 0; ks < 2; ks++) {
            const int kc = ks * 16 + 2 * (lane & 3);
            unsigned ah[4][4], al[4][4], bh[4][2], bl[4][2];
#pragma unroll
            for (int mt = 0; mt < 4; mt++) {
                int r0 = wm + mt * 16 + (lane >> 2);
                ah[mt][0] = *(const unsigned*)&Abh[r0 * LDK + kc];
                ah[mt][1] = *(const unsigned*)&Abh[(r0 + 8) * LDK + kc];
                ah[mt][2] = *(const unsigned*)&Abh[r0 * LDK + kc + 8];
                ah[mt][3] = *(const unsigned*)&Abh[(r0 + 8) * LDK + kc + 8];
                al[mt][0] = *(const unsigned*)&Abl[r0 * LDK + kc];
                al[mt][1] = *(const unsigned*)&Abl[(r0 + 8) * LDK + kc];
                al[mt][2] = *(const unsigned*)&Abl[r0 * LDK + kc + 8];
                al[mt][3] = *(const unsigned*)&Abl[(r0 + 8) * LDK + kc + 8];
            }
#pragma unroll
            for (int nt = 0; nt < 4; nt++) {
                int r0 = wn + nt * 8 + (lane >> 2);
                bh[nt][0] = *(const unsigned*)&Wbh[r0 * LDK + kc];
                bh[nt][1] = *(const unsigned*)&Wbh[r0 * LDK + kc + 8];
                bl[nt][0] = *(const unsigned*)&Wbl[r0 * LDK + kc];
                bl[nt][1] = *(const unsigned*)&Wbl[r0 * LDK + kc + 8];
            }
#pragma unroll
            for (int mt = 0; mt < 4; mt++)
#pragma unroll
                for (int nt = 0; nt < 4; nt++) {
                    MMA_BF16(c[mt][nt], ah[mt], bh[nt]);
                    MMA_BF16(c[mt][nt], ah[mt], bl[nt]);
                    MMA_BF16(c[mt][nt], al[mt], bh[nt]);
                }
        }
    };

    stage(0, 0);
    __syncthreads();
#pragma unroll 1
    for (int kt = 0; kt < 8; kt++) {
        const int cur = kt & 1;
        compute(cur);
        if (kt + 1 < 8) stage(kt + 1, cur ^ 1);
        __syncthreads();
    }

#pragma unroll
    for (int mt = 0; mt < 4; mt++)
#pragma unroll
        for (int nt = 0; nt < 4; nt++) {
            int row = wm + mt * 16 + (lane >> 2);
            int col = wn + nt * 8 + 2 * (lane & 3);
            Cs[row * 132 + col]           = c[mt][nt][0];
            Cs[row * 132 + col + 1]       = c[mt][nt][1];
            Cs[(row + 8) * 132 + col]     = c[mt][nt][2];
            Cs[(row + 8) * 132 + col + 1] = c[mt][nt][3];
        }
    __syncthreads();

#pragma unroll 1
    for (int j = 0; j < 16; j++) {
        int f4 = tid + j * 256;
        int row = f4 >> 5, c4 = (f4 & 31) * 4;
        float4 v = *(float4*)&Cs[row * 132 + c4];
        int n = n0 + c4;
        float4 bn = *(const float4*)&bias[n];
        v.x += bn.x; v.y += bn.y; v.z += bn.z; v.w += bn.w;
        int m = m0 + row;
        *(float4*)&Cm[(size_t)m * Nd + n] = v;
    }
}

// ---------------- region pooling (fp64 accumulate -> exact) ----------------
__global__ void pool_kernel()
{
    int i = blockIdx.x * 256 + threadIdx.x;
    if (i >= BB * NREG * CC) return;
    int c = i & 255;
    int r = (i >> 8) % 49;
    int b = i / (256 * 49);
    int head = c >> 5, d = c & 31;
    int base = (((b * NHD + head) * NREG + r) * SS) * HD + d;
    double sq = 0.0, sk = 0.0;
#pragma unroll 8
    for (int s = 0; s < SS; s++) {
        sq += (double)g_qseq[base + s * HD];
        sk += (double)g_kseq[base + s * HD];
    }
    g_qr[i] = sq * (1.0 / 64.0);
    g_kr[i] = sk * (1.0 / 64.0);
}

// ---------------- region routing top-4 (fp64 dots -> exact ordering) ----------------
__global__ void region_topk_kernel()
{
    __shared__ double qs[256];
    __shared__ double a[56];

    int bn = blockIdx.x;
    int b = bn / NREG, nq = bn % NREG;
    int tid = threadIdx.x;
    int warp = tid >> 5, lane = tid & 31;

    qs[tid] = g_qr[((size_t)b * NREG + nq) * CC + tid];
    __syncthreads();

    for (int r = warp; r < NREG; r += 8) {
        const double* kr = &g_kr[((size_t)b * NREG + r) * CC];
        double acc = 0.0;
#pragma unroll
        for (int j = 0; j < 8; j++) acc += qs[lane + 32 * j] * kr[lane + 32 * j];
#pragma unroll
        for (int off = 16; off; off >>= 1) acc += __shfl_xor_sync(0xffffffffu, acc, off);
        if (lane == 0) a[r] = acc;
    }
    __syncthreads();
    if (tid == 0) {
        for (int t = 0; t < TOPKR; t++) {
            double bm = -1e300; int bi = 0;
            for (int m = 0; m < NREG; m++)
                if (a[m] > bm) { bm = a[m]; bi = m; }   // strict > -> lowest index tie
            g_idx[(b * NREG + nq) * TOPKR + t] = bi;
            a[bi] = -1e300;
        }
    }
}

// ---------------- fused attention ----------------
// threshold-based top-32: binary search on orderable uints -> exact set,
// ballot-scan compaction, broadcast V gather via smem (wgt,idx). 3 CTAs/SM.
__global__ __launch_bounds__(256, 3)
void attn_kernel()
{
    extern __shared__ __align__(16) float asm_[];
    float* Qs = asm_;                         // [64][32]
    float* Kg = Qs + 64 * 32;                 // [256][32] xor-swizzled groups
    float* Vg = Kg + 256 * 32;                // [256][32]
    float2* buf = (float2*)(Vg + 256 * 32);   // [8 warps][32]

    int bid = blockIdx.x;
    int n = bid % NREG;
    int head = (bid / NREG) & 7;
    int b = bid / (NREG * NHD);
    int tid = threadIdx.x;
    int warp = tid >> 5, lane = tid & 31;
    const unsigned FULL = 0xffffffffu;

    {
        const float4* src = (const float4*)&g_qseq[(((size_t)(b * NHD + head) * NREG + n) * SS) * HD];
        for (int i4 = tid; i4 < 512; i4 += 256) {
            int row = i4 >> 3, g = i4 & 7;
            *(float4*)&Qs[row * 32 + g * 4] = src[i4];
        }
    }
    for (int t = 0; t < TOPKR; t++) {
        int rt = g_idx[(b * NREG + n) * TOPKR + t];
        const float4* ks = (const float4*)&g_kseq[(((size_t)(b * NHD + head) * NREG + rt) * SS) * HD];
        const float4* vs = (const float4*)&g_vseq[(((size_t)(b * NHD + head) * NREG + rt) * SS) * HD];
        for (int i4 = tid; i4 < 512; i4 += 256) {
            int lrow = i4 >> 3, g = i4 & 7;
            int row = t * 64 + lrow;
            *(float4*)&Kg[row * 32 + ((g ^ (row & 7)) << 2)] = ks[i4];
            *(float4*)&Vg[row * 32 + g * 4] = vs[i4];
        }
    }
    __syncthreads();

    float2* mybuf = (float2*)buf + warp * 32;

#pragma unroll 1
    for (int half = 0; half < 2; half++) {
        int rbase = warp * 8 + half * 4;
        float acc[4][8];
#pragma unroll
        for (int r = 0; r < 4; r++)
#pragma unroll
            for (int j = 0; j < 8; j++) acc[r][j] = 0.f;

#pragma unroll
        for (int g = 0; g < 8; g++) {
            int gsw = ((g ^ (lane & 7)) << 2);
            float4 qv[4];
#pragma unroll
            for (int r = 0; r < 4; r++) qv[r] = *(const float4*)&Qs[(rbase + r) * 32 + g * 4];
#pragma unroll
            for (int jh = 0; jh < 2; jh++) {
                float4 kv[4];
#pragma unroll
                for (int jj = 0; jj < 4; jj++)
                    kv[jj] = *(const float4*)&Kg[(lane + 32 * (jh * 4 + jj)) * 32 + gsw];
#pragma unroll
                for (int r = 0; r < 4; r++)
#pragma unroll
                    for (int jj = 0; jj < 4; jj++) {
                        acc[r][jh * 4 + jj] += qv[r].x * kv[jj].x;
                        acc[r][jh * 4 + jj] += qv[r].y * kv[jj].y;
                        acc[r][jh * 4 + jj] += qv[r].z * kv[jj].z;
                        acc[r][jh * 4 + jj] += qv[r].w * kv[jj].w;
                    }
            }
        }

#pragma unroll 1
        for (int r = 0; r < 4; r++) {
            unsigned u[8];
#pragma unroll
            for (int j = 0; j < 8; j++) {
                unsigned bts = __float_as_uint(acc[r][j]);
                u[j] = (bts & 0x80000000u) ? ~bts : (bts | 0x80000000u);
            }
            unsigned mx8 = u[0], mn8 = u[0];
#pragma unroll
            for (int j = 1; j < 8; j++) {
                mx8 = (u[j] > mx8) ? u[j] : mx8;
                mn8 = (u[j] < mn8) ? u[j] : mn8;
            }
            unsigned hi = __reduce_max_sync(FULL, mx8);
            unsigned lo = __reduce_min_sync(FULL, mn8) - 1u;
            float mxf = (hi & 0x80000000u) ? __uint_as_float(hi ^ 0x80000000u)
                                           : __uint_as_float(~hi);
            unsigned thr = hi;
            int found = 0;
            while (hi - lo > 1u) {
                unsigned t = lo + ((hi - lo) >> 1);
                int c = 0;
#pragma unroll
                for (int j = 0; j < 8; j++) c += (u[j] > t) ? 1 : 0;
                c = __reduce_add_sync(FULL, c);
                if (c == 32) { thr = t; found = 1; break; }
                if (c > 32) lo = t; else hi = t;
            }
            unsigned selmask = 0;
            if (found) {
#pragma unroll
                for (int j = 0; j < 8; j++)
                    if (u[j] > thr) selmask |= (1u << j);
            } else {
                int cg = 0;
#pragma unroll
                for (int j = 0; j < 8; j++) cg += (u[j] > hi) ? 1 : 0;
                int need = 32 - __reduce_add_sync(FULL, cg);
                int taken = 0;
#pragma unroll
                for (int j = 0; j < 8; j++) {
                    bool eq = (u[j] == hi);
                    unsigned bm = __ballot_sync(FULL, eq);
                    int before = taken + __popc(bm & ((1u << lane) - 1u));
                    if ((u[j] > hi) || (eq && before < need)) selmask |= (1u << j);
                    taken += __popc(bm);
                }
            }
            int cnt = __popc(selmask);
            int pos = cnt;
#pragma unroll
            for (int off = 1; off < 32; off <<= 1) {
                int nb = __shfl_up_sync(FULL, pos, off);
                if (lane >= off) pos += nb;
            }
            pos -= cnt;
#pragma unroll
            for (int j = 0; j < 8; j++) {
                if ((selmask >> j) & 1u) {
                    mybuf[pos] = make_float2(acc[r][j], __int_as_float(lane + 32 * j));
                    pos++;
                }
            }
            __syncwarp();
            float2 ent = mybuf[lane];
            float e = __expf((ent.x - mxf) * SCALE);
            float s = e;
#pragma unroll
            for (int off = 16; off; off >>= 1) s += __shfl_xor_sync(FULL, s, off);
            float wgt = e / s;
            __syncwarp();
            mybuf[lane] = make_float2(wgt, ent.y);   // stage (wgt, idx) for broadcast
            __syncwarp();
            float outv = 0.f;
#pragma unroll
            for (int k = 0; k < 32; k++) {
                float2 w2 = mybuf[k];                // LDS broadcast
                int ik = __float_as_int(w2.y);
                outv += w2.x * Vg[ik * 32 + lane];
            }
            int row = rbase + r;
            int hh = (n / 7) * 8 + (row >> 3);
            int ww = (n % 7) * 8 + (row & 7);
            int m = b * 3136 + hh * 56 + ww;
            g_attn_out[(size_t)m * CC + head * HD + lane] = outv;
            __syncwarp();
        }
    }
}

// ---------------- lepe (reads NHWC V copy, coalesced) ----------------
__global__ void lepe_kernel(const float* __restrict__ lepe_w, const float* __restrict__ lepe_b)
{
    int idx = blockIdx.x * 256 + threadIdx.x;
    int c = idx & 255;
    int m = idx >> 8;
    int b = m / (HH * WW);
    int hw = m % (HH * WW);
    int h = hw / WW, w = hw % WW;

    float acc = lepe_b[c];
#pragma unroll
    for (int i = 0; i < 3; i++) {
        int hh = h + i - 1;
        if (hh < 0 || hh >= HH) continue;
#pragma unroll
        for (int j = 0; j < 3; j++) {
            int ww = w + j - 1;
            if (ww < 0 || ww >= WW) continue;
            float vv = g_vhwc[((size_t)(b * 3136) + hh * 56 + ww) * 256 + c];
            acc += vv * lepe_w[c * 9 + i * 3 + j];
        }
    }
    g_attn_out[idx] += acc;
}

// ---------------- launch ----------------
extern "C" void kernel_launch(void* const* d_in, const int* in_sizes, int n_in,
                              void* d_out, int out_size)
{
    const float* x      = (const float*)d_in[0];
    const float* qkv_w  = (const float*)d_in[1];
    const float* qkv_b  = (const float*)d_in[2];
    const float* lepe_w = (const float*)d_in[3];
    const float* lepe_b = (const float*)d_in[4];
    const float* out_w  = (const float*)d_in[5];
    const float* out_b  = (const float*)d_in[6];
    float* out = (float*)d_out;

    float* attn_buf = nullptr;
    cudaGetSymbolAddress((void**)&attn_buf, g_attn_out);

    const int tf32_smem = 4 * 2 * 16 * TLD * 4;    // 69632
    const int bf16_smem = 2 * 128 * LDK * 4 * (int)sizeof(__nv_bfloat16);  // 81920
    const int attn_smem = (64 * 32 + 2 * 256 * 32) * 4 + 8 * 32 * 8;       // 75776

    cudaFuncSetAttribute(tf32_gemm<1>, cudaFuncAttributeMaxDynamicSharedMemorySize, tf32_smem);
    cudaFuncSetAttribute(bf16_gemm, cudaFuncAttributeMaxDynamicSharedMemorySize, bf16_smem);
    cudaFuncSetAttribute(attn_kernel, cudaFuncAttributeMaxDynamicSharedMemorySize, attn_smem);

    // 1) QKV GEMM: 2-split tf32 over all 768 columns, fused reshape scatter
    tf32_gemm<1><<<dim3(6, MM / 128), 256, tf32_smem>>>(x, qkv_w, qkv_b, nullptr, 768, 0);

    // 2) region pooling (fp64)
    pool_kernel<<<(BB * NREG * CC + 255) / 256, 256>>>();

    // 3) region routing top-4 (fp64 exact)
    region_topk_kernel<<<BB * NREG, 256>>>();

    // 4) fused attention (threshold top-32)
    attn_kernel<<<BB * NHD * NREG, 256, attn_smem>>>();

    // 5) lepe
    lepe_kernel<<<(MM * CC) / 256, 256>>>(lepe_w, lepe_b);

    // 6) output projection (bf16x3)
    bf16_gemm<<<dim3(CC / 128, MM / 128), 256, bf16_smem>>>(attn_buf, out_w, out_b, out, 256);
}